// round 11
// baseline (speedup 1.0000x reference)
#include <cuda_runtime.h>
#include <math.h>
#include <stdint.h>

// ---------------- scratch (no allocation allowed) ----------------
__device__ float g_spart_v[8 * 16384];      // partial scores, visual (nblk, b*128+t)
__device__ float g_spart_a[8 * 16384];      // partial scores, audio
__device__ float g_spart_h[8 * 2048];       // partial scores, hidden (nblk, l*128+b)
__device__ float g_v1v[128 * 1024];
__device__ float g_v1a[128 * 1024];
__device__ float g_v1h[128 * 1024];
__device__ float g_ctxv[128 * 1024];
__device__ float g_ctxa[128 * 1024];
__device__ float g_ctxh[128 * 1024];
__device__ float g_cstack[128 * 3 * 512];   // (b, slot, 512)
__device__ float g_v1c[128 * 512];
__device__ float g_v2c[128 * 3 * 512];
__device__ float g_gates[128 * 4096];
// tf32-RNA-rounded + k-permuted copies for the fast score GEMMs
__device__ float g_vr[16384 * 1024];
__device__ float g_ar[16384 * 1024];
__device__ float g_hr[2048 * 1024];
__device__ float g_w1v[1024 * 1024];
__device__ float g_w1a[1024 * 1024];
__device__ float g_w1h[1024 * 1024];

__device__ __forceinline__ unsigned cvt_tf32(float x) {
    unsigned r;
    asm("cvt.rna.tf32.f32 %0, %1;" : "=r"(r) : "f"(x));
    return r;
}
__device__ __forceinline__ float rna_tf32(float x) {
    return __uint_as_float(cvt_tf32(x));
}

__device__ __forceinline__ void cp_async16(unsigned smem_dst, const float* src, int bytes) {
    asm volatile("cp.async.cg.shared.global [%0], [%1], 16, %2;\n"
                 :: "r"(smem_dst), "l"(src), "r"(bytes));
}

// ---------------- tf32 RNA round + k-group permute (z-batched) -----------
// For each 16-float group along k: out[4*(k&3)+(k>>2)] = rna(in[k]).
struct RPW { const float4* src[3]; float4* dst[3]; int ng[3]; };
__global__ void round_perm_tf32_z(RPW w)
{
    int g = blockIdx.x * blockDim.x + threadIdx.x;
    const int z = blockIdx.z;
    if (g < w.ng[z]) {
        const float4* s = w.src[z] + (size_t)g * 4;
        float4 v0 = s[0], v1 = s[1], v2 = s[2], v3 = s[3];
        float4* d = w.dst[z] + (size_t)g * 4;
        d[0] = make_float4(rna_tf32(v0.x), rna_tf32(v1.x), rna_tf32(v2.x), rna_tf32(v3.x));
        d[1] = make_float4(rna_tf32(v0.y), rna_tf32(v1.y), rna_tf32(v2.y), rna_tf32(v3.y));
        d[2] = make_float4(rna_tf32(v0.z), rna_tf32(v1.z), rna_tf32(v2.z), rna_tf32(v3.z));
        d[3] = make_float4(rna_tf32(v0.w), rna_tf32(v1.w), rna_tf32(v2.w), rna_tf32(v3.w));
    }
}

// =======================================================================
// FAST score GEMM, K-tile 32 (two 16-k-group planes per stage).
// smem layout: A [2 stages][2 groups][128][16], B same, then s_ws[4][128].
// Bank pattern identical to the proven stride-16 layout (conflict-free).
// =======================================================================
#define TCSM_FLOATS (2 * 8192 + 512)
#define TCSM_BYTES (TCSM_FLOATS * 4)   // 67584

struct STask {
    const float* A;
    const float* B;
    const float* v1;
    const float* w2;
    float* spart;
    int M;
    int shift;
    int mask;
    int pad;
};
struct STasks { STask t[3]; };

__global__ __launch_bounds__(256) void mma_perm(STasks ts, int nk)
{
    extern __shared__ float sm[];
    float* Ab   = sm;            // [2][2][128][16]
    float* Bb   = sm + 8192;     // [2][2][128][16]
    float* s_ws = sm + 16384;    // [4][128]

    const STask& tk = ts.t[blockIdx.z];
    const int bm = blockIdx.y * 128;
    if (bm >= tk.M) return;
    const int bn = blockIdx.x * 128;

    const int tid  = threadIdx.x;
    const int wid  = tid >> 5, lane = tid & 31;
    const int wm   = wid >> 2;
    const int wn   = wid & 3;
    const int gq   = lane >> 2;
    const int tq   = lane & 3;

    const float* A = tk.A + (size_t)bm * 1024;
    const float* B = tk.B + (size_t)bn * 1024;

    float acc[4][4][4];
#pragma unroll
    for (int i = 0; i < 4; i++)
#pragma unroll
        for (int j = 0; j < 4; j++)
#pragma unroll
            for (int v = 0; v < 4; v++) acc[i][j][v] = 0.0f;

    // prefetch: 1024 16B-chunks per operand per stage; 4 per thread each.
    auto prefetch = [&](int st, int k0) {
#pragma unroll
        for (int p = 0; p < 4; p++) {
            const int idx = p * 256 + tid;
            const int row = idx >> 3, ch = idx & 7;
            const int gsel = ch >> 2, c4 = (ch & 3) << 2;
            const int soff = (((st << 1) + gsel) * 128 + row) * 16 + c4;
            cp_async16((unsigned)__cvta_generic_to_shared(Ab + soff),
                       A + (size_t)row * 1024 + k0 + ch * 4, 16);
            cp_async16((unsigned)__cvta_generic_to_shared(Bb + soff),
                       B + (size_t)row * 1024 + k0 + ch * 4, 16);
        }
    };

    prefetch(0, 0);
    asm volatile("cp.async.commit_group;\n" ::: "memory");

    for (int it = 0; it < nk; it++) {
        asm volatile("cp.async.wait_group 0;\n" ::: "memory");
        __syncthreads();
        if (it + 1 < nk) {
            prefetch((it + 1) & 1, (it + 1) * 32);
            asm volatile("cp.async.commit_group;\n" ::: "memory");
        }
        const int s = it & 1;

#pragma unroll
        for (int g = 0; g < 2; g++) {
            const int plane = ((s << 1) + g) * 128;
            float4 bf[4];
#pragma unroll
            for (int nf = 0; nf < 4; nf++)
                bf[nf] = *reinterpret_cast<const float4*>(
                    &Bb[(plane + wn * 32 + nf * 8 + gq) * 16 + tq * 4]);

#pragma unroll
            for (int mf = 0; mf < 4; mf++) {
                const int mr = wm * 64 + mf * 16;
                float4 alo = *reinterpret_cast<const float4*>(
                    &Ab[(plane + mr + gq) * 16 + tq * 4]);
                float4 ahi = *reinterpret_cast<const float4*>(
                    &Ab[(plane + mr + gq + 8) * 16 + tq * 4]);
#pragma unroll
                for (int nf = 0; nf < 4; nf++) {
                    float* c = acc[mf][nf];
                    asm volatile(
                        "mma.sync.aligned.m16n8k8.row.col.f32.tf32.tf32.f32 "
                        "{%0,%1,%2,%3}, {%4,%5,%6,%7}, {%8,%9}, {%0,%1,%2,%3};\n"
                        : "+f"(c[0]), "+f"(c[1]), "+f"(c[2]), "+f"(c[3])
                        : "r"(__float_as_uint(alo.x)), "r"(__float_as_uint(ahi.x)),
                          "r"(__float_as_uint(alo.y)), "r"(__float_as_uint(ahi.y)),
                          "r"(__float_as_uint(bf[nf].x)), "r"(__float_as_uint(bf[nf].y)));
                }
#pragma unroll
                for (int nf = 0; nf < 4; nf++) {
                    float* c = acc[mf][nf];
                    asm volatile(
                        "mma.sync.aligned.m16n8k8.row.col.f32.tf32.tf32.f32 "
                        "{%0,%1,%2,%3}, {%4,%5,%6,%7}, {%8,%9}, {%0,%1,%2,%3};\n"
                        : "+f"(c[0]), "+f"(c[1]), "+f"(c[2]), "+f"(c[3])
                        : "r"(__float_as_uint(alo.z)), "r"(__float_as_uint(ahi.z)),
                          "r"(__float_as_uint(alo.w)), "r"(__float_as_uint(ahi.w)),
                          "r"(__float_as_uint(bf[nf].z)), "r"(__float_as_uint(bf[nf].w)));
                }
            }
        }
    }

    // ---- score epilogue ----
    const float* v1 = tk.v1;
    const float* w2 = tk.w2;
    const int shift = tk.shift, mask = tk.mask;
#pragma unroll
    for (int mf = 0; mf < 4; mf++) {
        const int row0 = bm + wm * 64 + mf * 16 + gq;
        const int row1 = row0 + 8;
        const size_t v1b0 = (size_t)((row0 >> shift) & mask) * 1024;
        const size_t v1b1 = (size_t)((row1 >> shift) & mask) * 1024;
        float s0 = 0.f, s1 = 0.f;
#pragma unroll
        for (int nf = 0; nf < 4; nf++) {
            const int col = bn + wn * 32 + nf * 8 + tq * 2;
            const float w0 = w2[col], w1 = w2[col + 1];
            s0 += tanhf(acc[mf][nf][0] + v1[v1b0 + col])     * w0
                + tanhf(acc[mf][nf][1] + v1[v1b0 + col + 1]) * w1;
            s1 += tanhf(acc[mf][nf][2] + v1[v1b1 + col])     * w0
                + tanhf(acc[mf][nf][3] + v1[v1b1 + col + 1]) * w1;
        }
        s0 += __shfl_xor_sync(0xffffffffu, s0, 1);
        s0 += __shfl_xor_sync(0xffffffffu, s0, 2);
        s1 += __shfl_xor_sync(0xffffffffu, s1, 1);
        s1 += __shfl_xor_sync(0xffffffffu, s1, 2);
        if (tq == 0) {
            s_ws[wn * 128 + wm * 64 + mf * 16 + gq]     = s0;
            s_ws[wn * 128 + wm * 64 + mf * 16 + gq + 8] = s1;
        }
    }
    __syncthreads();
    for (int i = tid; i < 128; i += 256) {
        float v = s_ws[0 * 128 + i] + s_ws[1 * 128 + i]
                + s_ws[2 * 128 + i] + s_ws[3 * 128 + i];
        tk.spart[(size_t)blockIdx.x * tk.M + bm + i] = v;
    }
}

// =======================================================================
// General mma.sync TF32 GEMM (all non-score GEMMs) — unchanged.
// =======================================================================
#define BM 128
#define BN 128
#define BK 16
#define LDSS 20

struct Seg {
    const float* A;
    const float* B;
    long long lda;
    long long ldb;
    int K;
    int pad;
};
struct Task {
    Seg seg[3];
    float* C;
    const float* bias1;
    const float* bias2;
    long long ldc;
    int nseg;
    int pad;
};
struct Tasks4 { Task t[4]; };

__global__ __launch_bounds__(256, 2) void mma_tn_g(int M, int N, Tasks4 ts)
{
    __shared__ float As[2][BM][LDSS];
    __shared__ float Bs[2][BN][LDSS];

    const Task& tk = ts.t[blockIdx.z];

    const int tid  = threadIdx.x;
    const int wid  = tid >> 5, lane = tid & 31;
    const int wm   = wid >> 2;
    const int wn   = wid & 3;
    const int gq   = lane >> 2;
    const int tq   = lane & 3;

    const int bm = blockIdx.y * BM;
    const int bn = blockIdx.x * BN;

    const int lr = tid >> 2;
    const int lc = (tid & 3) << 2;

    float acc[4][4][4];
#pragma unroll
    for (int i = 0; i < 4; i++)
#pragma unroll
        for (int j = 0; j < 4; j++)
#pragma unroll
            for (int v = 0; v < 4; v++) acc[i][j][v] = 0.0f;

    int total_nk = 0;
    for (int i = 0; i < tk.nseg; i++) total_nk += tk.seg[i].K >> 4;

    auto prefetch = [&](int st, int si, int k0) {
        const float* Aseg = tk.seg[si].A;
        const float* Bseg = tk.seg[si].B;
        const long long lda = tk.seg[si].lda;
        const long long ldb = tk.seg[si].ldb;
#pragma unroll
        for (int part = 0; part < 2; part++) {
            int r = lr + part * 64;
            const float* asrc = Aseg + (size_t)(bm + r) * lda + k0 + lc;
            unsigned ad = (unsigned)__cvta_generic_to_shared(&As[st][r][lc]);
            cp_async16(ad, asrc, 16);
            int gn = bn + r;
            int ok = (gn < N);
            const float* bsrc = Bseg + (size_t)(ok ? gn : 0) * ldb + k0 + lc;
            unsigned bd = (unsigned)__cvta_generic_to_shared(&Bs[st][r][lc]);
            cp_async16(bd, bsrc, ok ? 16 : 0);
        }
    };

    prefetch(0, 0, 0);
    asm volatile("cp.async.commit_group;\n" ::: "memory");
    int psi = 0, pk0 = BK;
    if (pk0 >= tk.seg[0].K) { psi = 1; pk0 = 0; }

    for (int it = 0; it < total_nk; it++) {
        asm volatile("cp.async.wait_group 0;\n" ::: "memory");
        __syncthreads();
        if (it + 1 < total_nk) {
            prefetch((it + 1) & 1, psi, pk0);
            asm volatile("cp.async.commit_group;\n" ::: "memory");
            pk0 += BK;
            if (pk0 >= tk.seg[psi].K) { psi = (psi < 2) ? psi + 1 : psi; pk0 = 0; }
        }
        const int s = it & 1;

#pragma unroll
        for (int kk = 0; kk < BK; kk += 8) {
            unsigned af[4][4], bfr[4][2];
#pragma unroll
            for (int mf = 0; mf < 4; mf++) {
                const int mr = wm * 64 + mf * 16;
                af[mf][0] = cvt_tf32(As[s][mr + gq    ][kk + tq    ]);
                af[mf][1] = cvt_tf32(As[s][mr + gq + 8][kk + tq    ]);
                af[mf][2] = cvt_tf32(As[s][mr + gq    ][kk + tq + 4]);
                af[mf][3] = cvt_tf32(As[s][mr + gq + 8][kk + tq + 4]);
            }
#pragma unroll
            for (int nf = 0; nf < 4; nf++) {
                const int nr = wn * 32 + nf * 8;
                bfr[nf][0] = cvt_tf32(Bs[s][nr + gq][kk + tq    ]);
                bfr[nf][1] = cvt_tf32(Bs[s][nr + gq][kk + tq + 4]);
            }
#pragma unroll
            for (int mf = 0; mf < 4; mf++)
#pragma unroll
                for (int nf = 0; nf < 4; nf++) {
                    float* c = acc[mf][nf];
                    asm volatile(
                        "mma.sync.aligned.m16n8k8.row.col.f32.tf32.tf32.f32 "
                        "{%0,%1,%2,%3}, {%4,%5,%6,%7}, {%8,%9}, {%0,%1,%2,%3};\n"
                        : "+f"(c[0]), "+f"(c[1]), "+f"(c[2]), "+f"(c[3])
                        : "r"(af[mf][0]), "r"(af[mf][1]), "r"(af[mf][2]), "r"(af[mf][3]),
                          "r"(bfr[nf][0]), "r"(bfr[nf][1]));
                }
        }
    }

    float* C = tk.C;
    const long long ldc = tk.ldc;
    const float* b1 = tk.bias1;
    const float* b2 = tk.bias2;
#pragma unroll
    for (int mf = 0; mf < 4; mf++) {
        const int row = bm + wm * 64 + mf * 16 + gq;
#pragma unroll
        for (int nf = 0; nf < 4; nf++) {
            const int col = bn + wn * 32 + nf * 8 + tq * 2;
            if (col < N) {
                float2 v0 = make_float2(acc[mf][nf][0], acc[mf][nf][1]);
                float2 v1x = make_float2(acc[mf][nf][2], acc[mf][nf][3]);
                if (b1) {
                    float bx = b1[col], by = b1[col + 1];
                    v0.x += bx; v0.y += by; v1x.x += bx; v1x.y += by;
                }
                if (b2) {
                    float bx = b2[col], by = b2[col + 1];
                    v0.x += bx; v0.y += by; v1x.x += bx; v1x.y += by;
                }
                size_t i0 = (size_t)row * ldc + col;
                size_t i1 = (size_t)(row + 8) * ldc + col;
                *reinterpret_cast<float2*>(&C[i0]) = v0;
                *reinterpret_cast<float2*>(&C[i1]) = v1x;
            }
        }
    }
}

// ---------------- attention part 2: gather partials, softmax, context -----
__global__ __launch_bounds__(256) void attn2(
    int T, int nb, int Msp,
    const float* __restrict__ spart, int sp_sb, int sp_st,
    const float* __restrict__ vec2, long long vv_sb, long long vv_st,
    float* __restrict__ out, long long out_sb)
{
    __shared__ float s_score[128];
    __shared__ float s_red[256];

    const int b = blockIdx.x;
    const int tid = threadIdx.x;

    for (int t = tid; t < T; t += 256) {
        float s = 0.f;
        const float* p = spart + (size_t)b * sp_sb + (size_t)t * sp_st;
#pragma unroll
        for (int k = 0; k < 8; k++)
            if (k < nb) s += p[(size_t)k * Msp];
        s_score[t] = s;
    }
    __syncthreads();

    float m = -1e30f;
    for (int t = tid; t < T; t += 256) m = fmaxf(m, s_score[t]);
    s_red[tid] = m;
    __syncthreads();
    for (int s = 128; s > 0; s >>= 1) {
        if (tid < s) s_red[tid] = fmaxf(s_red[tid], s_red[tid + s]);
        __syncthreads();
    }
    const float mx = s_red[0];
    __syncthreads();
    float lsum = 0.f;
    for (int t = tid; t < T; t += 256) {
        float e = expf(s_score[t] - mx);
        s_score[t] = e;
        lsum += e;
    }
    s_red[tid] = lsum;
    __syncthreads();
    for (int s = 128; s > 0; s >>= 1) {
        if (tid < s) s_red[tid] += s_red[tid + s];
        __syncthreads();
    }
    const float inv = 1.0f / s_red[0];

    const int d = blockIdx.y * 256 + tid;
    const float* base = vec2 + (size_t)b * vv_sb + d;
    float a0 = 0.f, a1 = 0.f, a2 = 0.f, a3 = 0.f;
    for (int t = 0; t < T; t += 4) {
        a0 += s_score[t    ] * base[(size_t)(t    ) * vv_st];
        a1 += s_score[t + 1] * base[(size_t)(t + 1) * vv_st];
        a2 += s_score[t + 2] * base[(size_t)(t + 2) * vv_st];
        a3 += s_score[t + 3] * base[(size_t)(t + 3) * vv_st];
    }
    out[(size_t)b * out_sb + d] = ((a0 + a1) + (a2 + a3)) * inv;
}

// ---------------- fused attention (tiny final T=3) ------
__global__ __launch_bounds__(256) void attn_ctx(
    int T, int E, int D,
    const float* __restrict__ v1,
    const float* __restrict__ v2, long long v2_sb, long long v2_st,
    const float* __restrict__ w2,
    const float* __restrict__ vec2, long long vv_sb, long long vv_st,
    float* __restrict__ out, long long out_sb)
{
    __shared__ float s_v1[1024];
    __shared__ float s_w2[1024];
    __shared__ float s_score[128];
    __shared__ float s_red[256];

    const int b = blockIdx.x;
    const int tid = threadIdx.x;
    for (int j = tid; j < E; j += 256) {
        s_v1[j] = v1[(size_t)b * E + j];
        s_w2[j] = w2[j];
    }
    __syncthreads();

    const int warp = tid >> 5, lane = tid & 31;
    for (int t = warp; t < T; t += 8) {
        const float* p = v2 + (long long)b * v2_sb + (long long)t * v2_st;
        float sum = 0.f;
        for (int j = lane; j < E; j += 32)
            sum += tanhf(s_v1[j] + p[j]) * s_w2[j];
#pragma unroll
        for (int o = 16; o > 0; o >>= 1) sum += __shfl_xor_sync(0xffffffffu, sum, o);
        if (lane == 0) s_score[t] = sum;
    }
    __syncthreads();

    float m = -1e30f;
    for (int t = tid; t < T; t += 256) m = fmaxf(m, s_score[t]);
    s_red[tid] = m;
    __syncthreads();
    for (int s = 128; s > 0; s >>= 1) {
        if (tid < s) s_red[tid] = fmaxf(s_red[tid], s_red[tid + s]);
        __syncthreads();
    }
    const float mx = s_red[0];
    __syncthreads();
    float lsum = 0.f;
    for (int t = tid; t < T; t += 256) {
        float e = expf(s_score[t] - mx);
        s_score[t] = e;
        lsum += e;
    }
    s_red[tid] = lsum;
    __syncthreads();
    for (int s = 128; s > 0; s >>= 1) {
        if (tid < s) s_red[tid] += s_red[tid + s];
        __syncthreads();
    }
    const float inv = 1.0f / s_red[0];

    for (int d = tid; d < D; d += 256) {
        const float* base = vec2 + (long long)b * vv_sb + d;
        float accd = 0.f;
        for (int t = 0; t < T; t++)
            accd += s_score[t] * base[(long long)t * vv_st];
        out[(long long)b * out_sb + d] = accd * inv;
    }
}

// ---------------- LSTM cell elementwise ----------------
__global__ void lstm_cell(const float* __restrict__ gates,
                          const float* __restrict__ cell,
                          float* __restrict__ h_out,
                          float* __restrict__ c_out)
{
    int idx = blockIdx.x * blockDim.x + threadIdx.x;
    int b = idx >> 10, j = idx & 1023;
    const float* g = gates + (size_t)b * 4096;
    float i_ = 1.f / (1.f + expf(-g[j]));
    float f_ = 1.f / (1.f + expf(-g[1024 + j]));
    float gg = tanhf(g[2048 + j]);
    float o_ = 1.f / (1.f + expf(-g[3072 + j]));
    float c = f_ * cell[idx] + i_ * gg;
    float h = o_ * tanhf(c);
    c_out[idx] = c;
    h_out[idx] = h;
}

// ---------------- host-side task builders ----------------
static Task mk_task(const float* A, long long lda, const float* B, long long ldb,
                    int K, float* C, long long ldc,
                    const float* b1, const float* b2)
{
    Task t;
    for (int i = 0; i < 3; i++) { t.seg[i].A = A; t.seg[i].B = B; t.seg[i].lda = lda;
                                  t.seg[i].ldb = ldb; t.seg[i].K = K; t.seg[i].pad = 0; }
    t.nseg = 1; t.C = C; t.ldc = ldc; t.bias1 = b1; t.bias2 = b2; t.pad = 0;
    return t;
}

static void launch_tasks(int M, int N, const Task* tasks, int nz)
{
    Tasks4 ts;
    for (int i = 0; i < 4; i++) ts.t[i] = tasks[i < nz ? i : 0];
    dim3 grid((N + BN - 1) / BN, M / BM, nz);
    mma_tn_g<<<grid, 256>>>(M, N, ts);
}

extern "C" void kernel_launch(void* const* d_in, const int* in_sizes, int n_in,
                              void* d_out, int out_size)
{
    const float* input   = (const float*)d_in[0];   // [128,1,1024]
    const float* visual  = (const float*)d_in[1];   // [128,128,1024]
    const float* audio   = (const float*)d_in[2];   // [128,128,1024]
    const float* hstates = (const float*)d_in[3];   // [16,128,1024]
    const float* cell    = (const float*)d_in[4];   // [128,1024]
    const float* context = (const float*)d_in[5];   // [128,1,512]
    const float* Wv0 = (const float*)d_in[6];
    const float* Wv1 = (const float*)d_in[7];
    const float* Wv2 = (const float*)d_in[8];
    const float* Wa0 = (const float*)d_in[9];
    const float* Wa1 = (const float*)d_in[10];
    const float* Wa2 = (const float*)d_in[11];
    const float* Wh0 = (const float*)d_in[12];
    const float* Wh1 = (const float*)d_in[13];
    const float* Wh2 = (const float*)d_in[14];
    const float* Wc0 = (const float*)d_in[15];
    const float* Wc1 = (const float*)d_in[16];
    const float* Wc2 = (const float*)d_in[17];
    const float* Wac = (const float*)d_in[18];
    const float* bac = (const float*)d_in[19];
    const float* Wvc = (const float*)d_in[20];
    const float* bvc = (const float*)d_in[21];
    const float* Whc = (const float*)d_in[22];
    const float* bhc = (const float*)d_in[23];
    const float* W_ih = (const float*)d_in[24];     // [4096,1536]
    const float* W_hh = (const float*)d_in[25];     // [4096,1024]
    const float* b_ih = (const float*)d_in[26];
    const float* b_hh = (const float*)d_in[27];
    const float* W_out = (const float*)d_in[28];    // [20000,1024]
    const float* b_out = (const float*)d_in[29];

    float* out = (float*)d_out;
    float* out_logits = out;
    float* out_h      = out + 2560000;
    float* out_c      = out + 2560000 + 131072;
    float* out_fctx   = out + 2560000 + 131072 + 131072;

    float *spv, *spa, *sph, *v1v, *v1a, *v1h, *ctxv, *ctxa, *ctxh,
          *cstack, *v1c, *v2c, *gates, *vr, *ar, *hr, *w1v, *w1a, *w1h;
    cudaGetSymbolAddress((void**)&spv, g_spart_v);
    cudaGetSymbolAddress((void**)&spa, g_spart_a);
    cudaGetSymbolAddress((void**)&sph, g_spart_h);
    cudaGetSymbolAddress((void**)&v1v, g_v1v);
    cudaGetSymbolAddress((void**)&v1a, g_v1a);
    cudaGetSymbolAddress((void**)&v1h, g_v1h);
    cudaGetSymbolAddress((void**)&ctxv, g_ctxv);
    cudaGetSymbolAddress((void**)&ctxa, g_ctxa);
    cudaGetSymbolAddress((void**)&ctxh, g_ctxh);
    cudaGetSymbolAddress((void**)&cstack, g_cstack);
    cudaGetSymbolAddress((void**)&v1c, g_v1c);
    cudaGetSymbolAddress((void**)&v2c, g_v2c);
    cudaGetSymbolAddress((void**)&gates, g_gates);
    cudaGetSymbolAddress((void**)&vr, g_vr);
    cudaGetSymbolAddress((void**)&ar, g_ar);
    cudaGetSymbolAddress((void**)&hr, g_hr);
    cudaGetSymbolAddress((void**)&w1v, g_w1v);
    cudaGetSymbolAddress((void**)&w1a, g_w1a);
    cudaGetSymbolAddress((void**)&w1h, g_w1h);

    const float* hidden = hstates + (size_t)15 * 128 * 1024;  // hidden_states[-1]

    // [1] query projections: v1 = q @ W0^T  (3 tasks, ONE launch)
    {
        Task t[3] = {
            mk_task(context, 512, Wv0, 512, 512, v1v, 1024, nullptr, nullptr),
            mk_task(context, 512, Wa0, 512, 512, v1a, 1024, nullptr, nullptr),
            mk_task(context, 512, Wh0, 512, 512, v1h, 1024, nullptr, nullptr),
        };
        launch_tasks(128, 1024, t, 3);
    }
    // [2] round+permute activations (z=3, per-z sizes)
    {
        RPW w;
        w.src[0] = (const float4*)visual;  w.dst[0] = (float4*)vr; w.ng[0] = 1048576;
        w.src[1] = (const float4*)audio;   w.dst[1] = (float4*)ar; w.ng[1] = 1048576;
        w.src[2] = (const float4*)hstates; w.dst[2] = (float4*)hr; w.ng[2] = 131072;
        round_perm_tf32_z<<<dim3(4096, 1, 3), 256>>>(w);
    }
    // [3] round+permute weights (z=3)
    {
        RPW w;
        w.src[0] = (const float4*)Wv1; w.dst[0] = (float4*)w1v; w.ng[0] = 65536;
        w.src[1] = (const float4*)Wa1; w.dst[1] = (float4*)w1a; w.ng[1] = 65536;
        w.src[2] = (const float4*)Wh1; w.dst[2] = (float4*)w1h; w.ng[2] = 65536;
        round_perm_tf32_z<<<dim3(256, 1, 3), 256>>>(w);
    }
    // [4] fast score GEMMs: visual + audio + hidden, ONE launch (target ncu slot)
    {
        STasks st;
        st.t[0] = { vr, w1v, v1v, Wv2, spv, 16384, 7, 127, 0 };
        st.t[1] = { ar, w1a, v1a, Wa2, spa, 16384, 7, 127, 0 };
        st.t[2] = { hr, w1h, v1h, Wh2, sph, 2048,  0, 127, 0 };
        cudaFuncSetAttribute(mma_perm, cudaFuncAttributeMaxDynamicSharedMemorySize,
                             TCSM_BYTES);
        mma_perm<<<dim3(8, 128, 3), 256, TCSM_BYTES>>>(st, 1024 / 32);
    }

    // --- attention: softmax over partial scores + context accumulation ---
    attn2<<<dim3(128, 4), 256>>>(128, 8, 16384, spv, 128, 1,
                                 visual, 128 * 1024, 1024, ctxv, 1024);
    attn2<<<dim3(128, 4), 256>>>(128, 8, 16384, spa, 128, 1,
                                 audio, 128 * 1024, 1024, ctxa, 1024);
    attn2<<<dim3(128, 4), 256>>>(16, 8, 2048, sph, 1, 128,
                                 hstates, 1024, 128 * 1024, ctxh, 1024);

    // --- context stack (3 tasks) + Wc0 query projection (1 task): ONE launch ---
    {
        Task t[4] = {
            mk_task(ctxa,   1024, Wac, 1024, 1024, cstack + 0,    1536, bac, nullptr),
            mk_task(ctxv,   1024, Wvc, 1024, 1024, cstack + 512,  1536, bvc, nullptr),
            mk_task(ctxh,   1024, Whc, 1024, 1024, cstack + 1024, 1536, bhc, nullptr),
            mk_task(hidden, 1024, Wc0, 1024, 1024, v1c,           512,  nullptr, nullptr),
        };
        launch_tasks(128, 512, t, 4);
    }

    // --- v2c = cstack @ Wc1^T ---
    {
        Task t = mk_task(cstack, 512, Wc1, 512, 512, v2c, 512, nullptr, nullptr);
        launch_tasks(384, 512, &t, 1);
    }
    attn_ctx<<<128, 256>>>(3, 512, 512, v1c, v2c, 3 * 512, 512, Wc2,
                           cstack, 3 * 512, 512, out_fctx, 512);

    // --- LSTM gates: 3 K-segments accumulated in ONE launch ---
    {
        Task t = mk_task(out_fctx, 512, W_ih, 1536, 512, gates, 4096, b_ih, b_hh);
        t.seg[1].A = input;  t.seg[1].lda = 1024; t.seg[1].B = W_ih + 512; t.seg[1].ldb = 1536; t.seg[1].K = 1024;
        t.seg[2].A = hidden; t.seg[2].lda = 1024; t.seg[2].B = W_hh;       t.seg[2].ldb = 1024; t.seg[2].K = 1024;
        t.nseg = 3;
        launch_tasks(128, 4096, &t, 1);
    }

    lstm_cell<<<512, 256>>>(gates, cell, out_h, out_c);

    // --- logits = h_new @ W_out^T + b_out ---
    {
        Task t = mk_task(out_h, 1024, W_out, 1024, 1024, out_logits, 20000, b_out, nullptr);
        launch_tasks(128, 20000, &t, 1);
    }
}

// round 12
// speedup vs baseline: 1.0047x; 1.0047x over previous
#include <cuda_runtime.h>
#include <math.h>
#include <stdint.h>

// ---------------- scratch (no allocation allowed) ----------------
__device__ float g_spart_v[8 * 16384];      // partial scores, visual (nblk, b*128+t)
__device__ float g_spart_a[8 * 16384];      // partial scores, audio
__device__ float g_spart_h[8 * 2048];       // partial scores, hidden (nblk, l*128+b)
__device__ float g_v1v[128 * 1024];
__device__ float g_v1a[128 * 1024];
__device__ float g_v1h[128 * 1024];
__device__ float g_ctxv[128 * 1024];
__device__ float g_ctxa[128 * 1024];
__device__ float g_ctxh[128 * 1024];
__device__ float g_cstack[128 * 3 * 512];   // (b, slot, 512)
__device__ float g_v1c[128 * 512];
__device__ float g_v2c[128 * 3 * 512];
__device__ float g_gates[128 * 4096];
// tf32-RNA-rounded + k-permuted copies for the fast score GEMMs
__device__ float g_vr[16384 * 1024];
__device__ float g_ar[16384 * 1024];
__device__ float g_hr[2048 * 1024];
__device__ float g_w1v[1024 * 1024];
__device__ float g_w1a[1024 * 1024];
__device__ float g_w1h[1024 * 1024];

__device__ __forceinline__ unsigned cvt_tf32(float x) {
    unsigned r;
    asm("cvt.rna.tf32.f32 %0, %1;" : "=r"(r) : "f"(x));
    return r;
}
__device__ __forceinline__ float rna_tf32(float x) {
    return __uint_as_float(cvt_tf32(x));
}

__device__ __forceinline__ void cp_async16(unsigned smem_dst, const float* src, int bytes) {
    asm volatile("cp.async.cg.shared.global [%0], [%1], 16, %2;\n"
                 :: "r"(smem_dst), "l"(src), "r"(bytes));
}

// ---------------- tf32 RNA round + k-group permute (z-batched) -----------
// For each 16-float group along k: out[4*(k&3)+(k>>2)] = rna(in[k]).
struct RPW { const float4* src[3]; float4* dst[3]; int ng[3]; };
__global__ void round_perm_tf32_z(RPW w)
{
    int g = blockIdx.x * blockDim.x + threadIdx.x;
    const int z = blockIdx.z;
    if (g < w.ng[z]) {
        const float4* s = w.src[z] + (size_t)g * 4;
        float4 v0 = s[0], v1 = s[1], v2 = s[2], v3 = s[3];
        float4* d = w.dst[z] + (size_t)g * 4;
        d[0] = make_float4(rna_tf32(v0.x), rna_tf32(v1.x), rna_tf32(v2.x), rna_tf32(v3.x));
        d[1] = make_float4(rna_tf32(v0.y), rna_tf32(v1.y), rna_tf32(v2.y), rna_tf32(v3.y));
        d[2] = make_float4(rna_tf32(v0.z), rna_tf32(v1.z), rna_tf32(v2.z), rna_tf32(v3.z));
        d[3] = make_float4(rna_tf32(v0.w), rna_tf32(v1.w), rna_tf32(v2.w), rna_tf32(v3.w));
    }
}

// =======================================================================
// FAST score GEMM, K-tile 16 (R9 structure), low-ALU addressing:
// per-stage base pointers precomputed; all fragment loads are
// LDS.128 [base + constant-imm]. MMA order identical to R9/R10.
// =======================================================================
#define PKT 16

struct STask {
    const float* A;
    const float* B;
    const float* v1;
    const float* w2;
    float* spart;
    int M;
    int shift;
    int mask;
    int pad;
};
struct STasks { STask t[3]; };

__global__ __launch_bounds__(256, 2) void mma_perm(STasks ts, int nk)
{
    __shared__ float4 As4[2][128][4];   // [stage][row][tq]
    __shared__ float4 Bs4[2][128][4];
    __shared__ float s_ws[4][128];

    const STask& tk = ts.t[blockIdx.z];
    const int bm = blockIdx.y * 128;
    if (bm >= tk.M) return;
    const int bn = blockIdx.x * 128;

    const int tid  = threadIdx.x;
    const int wid  = tid >> 5, lane = tid & 31;
    const int wm   = wid >> 2;
    const int wn   = wid & 3;
    const int gq   = lane >> 2;
    const int tq   = lane & 3;

    float acc[4][4][4];
#pragma unroll
    for (int i = 0; i < 4; i++)
#pragma unroll
        for (int j = 0; j < 4; j++)
#pragma unroll
            for (int v = 0; v < 4; v++) acc[i][j][v] = 0.0f;

    // ---- prefetch setup: running global pointers, pre-offset ----
    const int srow0 = tid >> 2, sch0 = tid & 3;          // chunk 0
    const int srow1 = (tid + 256) >> 2;                  // chunk 1 (same sch)
    const float* aSrc0 = tk.A + (size_t)(bm + srow0) * 1024 + sch0 * 4;
    const float* aSrc1 = tk.A + (size_t)(bm + srow1) * 1024 + sch0 * 4;
    const float* bSrc0 = tk.B + (size_t)(bn + srow0) * 1024 + sch0 * 4;
    const float* bSrc1 = tk.B + (size_t)(bn + srow1) * 1024 + sch0 * 4;
    const unsigned aDst0[2] = {
        (unsigned)__cvta_generic_to_shared(&As4[0][srow0][sch0]),
        (unsigned)__cvta_generic_to_shared(&As4[1][srow0][sch0]) };
    const unsigned aDst1[2] = {
        (unsigned)__cvta_generic_to_shared(&As4[0][srow1][sch0]),
        (unsigned)__cvta_generic_to_shared(&As4[1][srow1][sch0]) };
    const unsigned bDst0[2] = {
        (unsigned)__cvta_generic_to_shared(&Bs4[0][srow0][sch0]),
        (unsigned)__cvta_generic_to_shared(&Bs4[1][srow0][sch0]) };
    const unsigned bDst1[2] = {
        (unsigned)__cvta_generic_to_shared(&Bs4[0][srow1][sch0]),
        (unsigned)__cvta_generic_to_shared(&Bs4[1][srow1][sch0]) };

    auto prefetch = [&](int st, int k0) {
        cp_async16(aDst0[st], aSrc0 + k0, 16);
        cp_async16(aDst1[st], aSrc1 + k0, 16);
        cp_async16(bDst0[st], bSrc0 + k0, 16);
        cp_async16(bDst1[st], bSrc1 + k0, 16);
    };

    // ---- fragment base pointers (stage 0/1), constant offsets inside loop --
    const float4* aB[2] = { &As4[0][wm * 64 + gq][tq], &As4[1][wm * 64 + gq][tq] };
    const float4* bB[2] = { &Bs4[0][wn * 32 + gq][tq], &Bs4[1][wn * 32 + gq][tq] };

    prefetch(0, 0);
    asm volatile("cp.async.commit_group;\n" ::: "memory");

    for (int it = 0; it < nk; it++) {
        asm volatile("cp.async.wait_group 0;\n" ::: "memory");
        __syncthreads();
        if (it + 1 < nk) {
            prefetch((it + 1) & 1, (it + 1) * PKT);
            asm volatile("cp.async.commit_group;\n" ::: "memory");
        }
        const int s = it & 1;
        const float4* ap = aB[s];
        const float4* bp = bB[s];

        float4 bf[4];
#pragma unroll
        for (int nf = 0; nf < 4; nf++)
            bf[nf] = bp[nf * 32];            // (nf*8 rows) * 4 float4/row

#pragma unroll
        for (int mf = 0; mf < 4; mf++) {
            float4 alo = ap[mf * 64];        // (mf*16 rows) * 4
            float4 ahi = ap[mf * 64 + 32];   // +8 rows
#pragma unroll
            for (int nf = 0; nf < 4; nf++) {
                float* c = acc[mf][nf];
                asm volatile(
                    "mma.sync.aligned.m16n8k8.row.col.f32.tf32.tf32.f32 "
                    "{%0,%1,%2,%3}, {%4,%5,%6,%7}, {%8,%9}, {%0,%1,%2,%3};\n"
                    : "+f"(c[0]), "+f"(c[1]), "+f"(c[2]), "+f"(c[3])
                    : "r"(__float_as_uint(alo.x)), "r"(__float_as_uint(ahi.x)),
                      "r"(__float_as_uint(alo.y)), "r"(__float_as_uint(ahi.y)),
                      "r"(__float_as_uint(bf[nf].x)), "r"(__float_as_uint(bf[nf].y)));
            }
#pragma unroll
            for (int nf = 0; nf < 4; nf++) {
                float* c = acc[mf][nf];
                asm volatile(
                    "mma.sync.aligned.m16n8k8.row.col.f32.tf32.tf32.f32 "
                    "{%0,%1,%2,%3}, {%4,%5,%6,%7}, {%8,%9}, {%0,%1,%2,%3};\n"
                    : "+f"(c[0]), "+f"(c[1]), "+f"(c[2]), "+f"(c[3])
                    : "r"(__float_as_uint(alo.z)), "r"(__float_as_uint(ahi.z)),
                      "r"(__float_as_uint(alo.w)), "r"(__float_as_uint(ahi.w)),
                      "r"(__float_as_uint(bf[nf].z)), "r"(__float_as_uint(bf[nf].w)));
            }
        }
    }

    // ---- score epilogue ----
    const float* v1 = tk.v1;
    const float* w2 = tk.w2;
    const int shift = tk.shift, mask = tk.mask;
#pragma unroll
    for (int mf = 0; mf < 4; mf++) {
        const int row0 = bm + wm * 64 + mf * 16 + gq;
        const int row1 = row0 + 8;
        const size_t v1b0 = (size_t)((row0 >> shift) & mask) * 1024;
        const size_t v1b1 = (size_t)((row1 >> shift) & mask) * 1024;
        float s0 = 0.f, s1 = 0.f;
#pragma unroll
        for (int nf = 0; nf < 4; nf++) {
            const int col = bn + wn * 32 + nf * 8 + tq * 2;
            const float w0 = w2[col], w1 = w2[col + 1];
            s0 += tanhf(acc[mf][nf][0] + v1[v1b0 + col])     * w0
                + tanhf(acc[mf][nf][1] + v1[v1b0 + col + 1]) * w1;
            s1 += tanhf(acc[mf][nf][2] + v1[v1b1 + col])     * w0
                + tanhf(acc[mf][nf][3] + v1[v1b1 + col + 1]) * w1;
        }
        s0 += __shfl_xor_sync(0xffffffffu, s0, 1);
        s0 += __shfl_xor_sync(0xffffffffu, s0, 2);
        s1 += __shfl_xor_sync(0xffffffffu, s1, 1);
        s1 += __shfl_xor_sync(0xffffffffu, s1, 2);
        if (tq == 0) {
            s_ws[wn][wm * 64 + mf * 16 + gq]     = s0;
            s_ws[wn][wm * 64 + mf * 16 + gq + 8] = s1;
        }
    }
    __syncthreads();
    for (int i = tid; i < 128; i += 256) {
        float v = s_ws[0][i] + s_ws[1][i] + s_ws[2][i] + s_ws[3][i];
        tk.spart[(size_t)blockIdx.x * tk.M + bm + i] = v;
    }
}

// =======================================================================
// General mma.sync TF32 GEMM (all non-score GEMMs) — unchanged.
// =======================================================================
#define BM 128
#define BN 128
#define BK 16
#define LDSS 20

struct Seg {
    const float* A;
    const float* B;
    long long lda;
    long long ldb;
    int K;
    int pad;
};
struct Task {
    Seg seg[3];
    float* C;
    const float* bias1;
    const float* bias2;
    long long ldc;
    int nseg;
    int pad;
};
struct Tasks4 { Task t[4]; };

__global__ __launch_bounds__(256, 2) void mma_tn_g(int M, int N, Tasks4 ts)
{
    __shared__ float As[2][BM][LDSS];
    __shared__ float Bs[2][BN][LDSS];

    const Task& tk = ts.t[blockIdx.z];

    const int tid  = threadIdx.x;
    const int wid  = tid >> 5, lane = tid & 31;
    const int wm   = wid >> 2;
    const int wn   = wid & 3;
    const int gq   = lane >> 2;
    const int tq   = lane & 3;

    const int bm = blockIdx.y * BM;
    const int bn = blockIdx.x * BN;

    const int lr = tid >> 2;
    const int lc = (tid & 3) << 2;

    float acc[4][4][4];
#pragma unroll
    for (int i = 0; i < 4; i++)
#pragma unroll
        for (int j = 0; j < 4; j++)
#pragma unroll
            for (int v = 0; v < 4; v++) acc[i][j][v] = 0.0f;

    int total_nk = 0;
    for (int i = 0; i < tk.nseg; i++) total_nk += tk.seg[i].K >> 4;

    auto prefetch = [&](int st, int si, int k0) {
        const float* Aseg = tk.seg[si].A;
        const float* Bseg = tk.seg[si].B;
        const long long lda = tk.seg[si].lda;
        const long long ldb = tk.seg[si].ldb;
#pragma unroll
        for (int part = 0; part < 2; part++) {
            int r = lr + part * 64;
            const float* asrc = Aseg + (size_t)(bm + r) * lda + k0 + lc;
            unsigned ad = (unsigned)__cvta_generic_to_shared(&As[st][r][lc]);
            cp_async16(ad, asrc, 16);
            int gn = bn + r;
            int ok = (gn < N);
            const float* bsrc = Bseg + (size_t)(ok ? gn : 0) * ldb + k0 + lc;
            unsigned bd = (unsigned)__cvta_generic_to_shared(&Bs[st][r][lc]);
            cp_async16(bd, bsrc, ok ? 16 : 0);
        }
    };

    prefetch(0, 0, 0);
    asm volatile("cp.async.commit_group;\n" ::: "memory");
    int psi = 0, pk0 = BK;
    if (pk0 >= tk.seg[0].K) { psi = 1; pk0 = 0; }

    for (int it = 0; it < total_nk; it++) {
        asm volatile("cp.async.wait_group 0;\n" ::: "memory");
        __syncthreads();
        if (it + 1 < total_nk) {
            prefetch((it + 1) & 1, psi, pk0);
            asm volatile("cp.async.commit_group;\n" ::: "memory");
            pk0 += BK;
            if (pk0 >= tk.seg[psi].K) { psi = (psi < 2) ? psi + 1 : psi; pk0 = 0; }
        }
        const int s = it & 1;

#pragma unroll
        for (int kk = 0; kk < BK; kk += 8) {
            unsigned af[4][4], bfr[4][2];
#pragma unroll
            for (int mf = 0; mf < 4; mf++) {
                const int mr = wm * 64 + mf * 16;
                af[mf][0] = cvt_tf32(As[s][mr + gq    ][kk + tq    ]);
                af[mf][1] = cvt_tf32(As[s][mr + gq + 8][kk + tq    ]);
                af[mf][2] = cvt_tf32(As[s][mr + gq    ][kk + tq + 4]);
                af[mf][3] = cvt_tf32(As[s][mr + gq + 8][kk + tq + 4]);
            }
#pragma unroll
            for (int nf = 0; nf < 4; nf++) {
                const int nr = wn * 32 + nf * 8;
                bfr[nf][0] = cvt_tf32(Bs[s][nr + gq][kk + tq    ]);
                bfr[nf][1] = cvt_tf32(Bs[s][nr + gq][kk + tq + 4]);
            }
#pragma unroll
            for (int mf = 0; mf < 4; mf++)
#pragma unroll
                for (int nf = 0; nf < 4; nf++) {
                    float* c = acc[mf][nf];
                    asm volatile(
                        "mma.sync.aligned.m16n8k8.row.col.f32.tf32.tf32.f32 "
                        "{%0,%1,%2,%3}, {%4,%5,%6,%7}, {%8,%9}, {%0,%1,%2,%3};\n"
                        : "+f"(c[0]), "+f"(c[1]), "+f"(c[2]), "+f"(c[3])
                        : "r"(af[mf][0]), "r"(af[mf][1]), "r"(af[mf][2]), "r"(af[mf][3]),
                          "r"(bfr[nf][0]), "r"(bfr[nf][1]));
                }
        }
    }

    float* C = tk.C;
    const long long ldc = tk.ldc;
    const float* b1 = tk.bias1;
    const float* b2 = tk.bias2;
#pragma unroll
    for (int mf = 0; mf < 4; mf++) {
        const int row = bm + wm * 64 + mf * 16 + gq;
#pragma unroll
        for (int nf = 0; nf < 4; nf++) {
            const int col = bn + wn * 32 + nf * 8 + tq * 2;
            if (col < N) {
                float2 v0 = make_float2(acc[mf][nf][0], acc[mf][nf][1]);
                float2 v1x = make_float2(acc[mf][nf][2], acc[mf][nf][3]);
                if (b1) {
                    float bx = b1[col], by = b1[col + 1];
                    v0.x += bx; v0.y += by; v1x.x += bx; v1x.y += by;
                }
                if (b2) {
                    float bx = b2[col], by = b2[col + 1];
                    v0.x += bx; v0.y += by; v1x.x += bx; v1x.y += by;
                }
                size_t i0 = (size_t)row * ldc + col;
                size_t i1 = (size_t)(row + 8) * ldc + col;
                *reinterpret_cast<float2*>(&C[i0]) = v0;
                *reinterpret_cast<float2*>(&C[i1]) = v1x;
            }
        }
    }
}

// ---------------- attention part 2: gather partials, softmax, context -----
__global__ __launch_bounds__(256) void attn2(
    int T, int nb, int Msp,
    const float* __restrict__ spart, int sp_sb, int sp_st,
    const float* __restrict__ vec2, long long vv_sb, long long vv_st,
    float* __restrict__ out, long long out_sb)
{
    __shared__ float s_score[128];
    __shared__ float s_red[256];

    const int b = blockIdx.x;
    const int tid = threadIdx.x;

    for (int t = tid; t < T; t += 256) {
        float s = 0.f;
        const float* p = spart + (size_t)b * sp_sb + (size_t)t * sp_st;
#pragma unroll
        for (int k = 0; k < 8; k++)
            if (k < nb) s += p[(size_t)k * Msp];
        s_score[t] = s;
    }
    __syncthreads();

    float m = -1e30f;
    for (int t = tid; t < T; t += 256) m = fmaxf(m, s_score[t]);
    s_red[tid] = m;
    __syncthreads();
    for (int s = 128; s > 0; s >>= 1) {
        if (tid < s) s_red[tid] = fmaxf(s_red[tid], s_red[tid + s]);
        __syncthreads();
    }
    const float mx = s_red[0];
    __syncthreads();
    float lsum = 0.f;
    for (int t = tid; t < T; t += 256) {
        float e = expf(s_score[t] - mx);
        s_score[t] = e;
        lsum += e;
    }
    s_red[tid] = lsum;
    __syncthreads();
    for (int s = 128; s > 0; s >>= 1) {
        if (tid < s) s_red[tid] += s_red[tid + s];
        __syncthreads();
    }
    const float inv = 1.0f / s_red[0];

    const int d = blockIdx.y * 256 + tid;
    const float* base = vec2 + (size_t)b * vv_sb + d;
    float a0 = 0.f, a1 = 0.f, a2 = 0.f, a3 = 0.f;
    for (int t = 0; t < T; t += 4) {
        a0 += s_score[t    ] * base[(size_t)(t    ) * vv_st];
        a1 += s_score[t + 1] * base[(size_t)(t + 1) * vv_st];
        a2 += s_score[t + 2] * base[(size_t)(t + 2) * vv_st];
        a3 += s_score[t + 3] * base[(size_t)(t + 3) * vv_st];
    }
    out[(size_t)b * out_sb + d] = ((a0 + a1) + (a2 + a3)) * inv;
}

// ---------------- fused attention (tiny final T=3) ------
__global__ __launch_bounds__(256) void attn_ctx(
    int T, int E, int D,
    const float* __restrict__ v1,
    const float* __restrict__ v2, long long v2_sb, long long v2_st,
    const float* __restrict__ w2,
    const float* __restrict__ vec2, long long vv_sb, long long vv_st,
    float* __restrict__ out, long long out_sb)
{
    __shared__ float s_v1[1024];
    __shared__ float s_w2[1024];
    __shared__ float s_score[128];
    __shared__ float s_red[256];

    const int b = blockIdx.x;
    const int tid = threadIdx.x;
    for (int j = tid; j < E; j += 256) {
        s_v1[j] = v1[(size_t)b * E + j];
        s_w2[j] = w2[j];
    }
    __syncthreads();

    const int warp = tid >> 5, lane = tid & 31;
    for (int t = warp; t < T; t += 8) {
        const float* p = v2 + (long long)b * v2_sb + (long long)t * v2_st;
        float sum = 0.f;
        for (int j = lane; j < E; j += 32)
            sum += tanhf(s_v1[j] + p[j]) * s_w2[j];
#pragma unroll
        for (int o = 16; o > 0; o >>= 1) sum += __shfl_xor_sync(0xffffffffu, sum, o);
        if (lane == 0) s_score[t] = sum;
    }
    __syncthreads();

    float m = -1e30f;
    for (int t = tid; t < T; t += 256) m = fmaxf(m, s_score[t]);
    s_red[tid] = m;
    __syncthreads();
    for (int s = 128; s > 0; s >>= 1) {
        if (tid < s) s_red[tid] = fmaxf(s_red[tid], s_red[tid + s]);
        __syncthreads();
    }
    const float mx = s_red[0];
    __syncthreads();
    float lsum = 0.f;
    for (int t = tid; t < T; t += 256) {
        float e = expf(s_score[t] - mx);
        s_score[t] = e;
        lsum += e;
    }
    s_red[tid] = lsum;
    __syncthreads();
    for (int s = 128; s > 0; s >>= 1) {
        if (tid < s) s_red[tid] += s_red[tid + s];
        __syncthreads();
    }
    const float inv = 1.0f / s_red[0];

    for (int d = tid; d < D; d += 256) {
        const float* base = vec2 + (long long)b * vv_sb + d;
        float accd = 0.f;
        for (int t = 0; t < T; t++)
            accd += s_score[t] * base[(long long)t * vv_st];
        out[(long long)b * out_sb + d] = accd * inv;
    }
}

// ---------------- LSTM cell elementwise ----------------
__global__ void lstm_cell(const float* __restrict__ gates,
                          const float* __restrict__ cell,
                          float* __restrict__ h_out,
                          float* __restrict__ c_out)
{
    int idx = blockIdx.x * blockDim.x + threadIdx.x;
    int b = idx >> 10, j = idx & 1023;
    const float* g = gates + (size_t)b * 4096;
    float i_ = 1.f / (1.f + expf(-g[j]));
    float f_ = 1.f / (1.f + expf(-g[1024 + j]));
    float gg = tanhf(g[2048 + j]);
    float o_ = 1.f / (1.f + expf(-g[3072 + j]));
    float c = f_ * cell[idx] + i_ * gg;
    float h = o_ * tanhf(c);
    c_out[idx] = c;
    h_out[idx] = h;
}

// ---------------- host-side task builders ----------------
static Task mk_task(const float* A, long long lda, const float* B, long long ldb,
                    int K, float* C, long long ldc,
                    const float* b1, const float* b2)
{
    Task t;
    for (int i = 0; i < 3; i++) { t.seg[i].A = A; t.seg[i].B = B; t.seg[i].lda = lda;
                                  t.seg[i].ldb = ldb; t.seg[i].K = K; t.seg[i].pad = 0; }
    t.nseg = 1; t.C = C; t.ldc = ldc; t.bias1 = b1; t.bias2 = b2; t.pad = 0;
    return t;
}

static void launch_tasks(int M, int N, const Task* tasks, int nz)
{
    Tasks4 ts;
    for (int i = 0; i < 4; i++) ts.t[i] = tasks[i < nz ? i : 0];
    dim3 grid((N + BN - 1) / BN, M / BM, nz);
    mma_tn_g<<<grid, 256>>>(M, N, ts);
}

extern "C" void kernel_launch(void* const* d_in, const int* in_sizes, int n_in,
                              void* d_out, int out_size)
{
    const float* input   = (const float*)d_in[0];   // [128,1,1024]
    const float* visual  = (const float*)d_in[1];   // [128,128,1024]
    const float* audio   = (const float*)d_in[2];   // [128,128,1024]
    const float* hstates = (const float*)d_in[3];   // [16,128,1024]
    const float* cell    = (const float*)d_in[4];   // [128,1024]
    const float* context = (const float*)d_in[5];   // [128,1,512]
    const float* Wv0 = (const float*)d_in[6];
    const float* Wv1 = (const float*)d_in[7];
    const float* Wv2 = (const float*)d_in[8];
    const float* Wa0 = (const float*)d_in[9];
    const float* Wa1 = (const float*)d_in[10];
    const float* Wa2 = (const float*)d_in[11];
    const float* Wh0 = (const float*)d_in[12];
    const float* Wh1 = (const float*)d_in[13];
    const float* Wh2 = (const float*)d_in[14];
    const float* Wc0 = (const float*)d_in[15];
    const float* Wc1 = (const float*)d_in[16];
    const float* Wc2 = (const float*)d_in[17];
    const float* Wac = (const float*)d_in[18];
    const float* bac = (const float*)d_in[19];
    const float* Wvc = (const float*)d_in[20];
    const float* bvc = (const float*)d_in[21];
    const float* Whc = (const float*)d_in[22];
    const float* bhc = (const float*)d_in[23];
    const float* W_ih = (const float*)d_in[24];     // [4096,1536]
    const float* W_hh = (const float*)d_in[25];     // [4096,1024]
    const float* b_ih = (const float*)d_in[26];
    const float* b_hh = (const float*)d_in[27];
    const float* W_out = (const float*)d_in[28];    // [20000,1024]
    const float* b_out = (const float*)d_in[29];

    float* out = (float*)d_out;
    float* out_logits = out;
    float* out_h      = out + 2560000;
    float* out_c      = out + 2560000 + 131072;
    float* out_fctx   = out + 2560000 + 131072 + 131072;

    float *spv, *spa, *sph, *v1v, *v1a, *v1h, *ctxv, *ctxa, *ctxh,
          *cstack, *v1c, *v2c, *gates, *vr, *ar, *hr, *w1v, *w1a, *w1h;
    cudaGetSymbolAddress((void**)&spv, g_spart_v);
    cudaGetSymbolAddress((void**)&spa, g_spart_a);
    cudaGetSymbolAddress((void**)&sph, g_spart_h);
    cudaGetSymbolAddress((void**)&v1v, g_v1v);
    cudaGetSymbolAddress((void**)&v1a, g_v1a);
    cudaGetSymbolAddress((void**)&v1h, g_v1h);
    cudaGetSymbolAddress((void**)&ctxv, g_ctxv);
    cudaGetSymbolAddress((void**)&ctxa, g_ctxa);
    cudaGetSymbolAddress((void**)&ctxh, g_ctxh);
    cudaGetSymbolAddress((void**)&cstack, g_cstack);
    cudaGetSymbolAddress((void**)&v1c, g_v1c);
    cudaGetSymbolAddress((void**)&v2c, g_v2c);
    cudaGetSymbolAddress((void**)&gates, g_gates);
    cudaGetSymbolAddress((void**)&vr, g_vr);
    cudaGetSymbolAddress((void**)&ar, g_ar);
    cudaGetSymbolAddress((void**)&hr, g_hr);
    cudaGetSymbolAddress((void**)&w1v, g_w1v);
    cudaGetSymbolAddress((void**)&w1a, g_w1a);
    cudaGetSymbolAddress((void**)&w1h, g_w1h);

    const float* hidden = hstates + (size_t)15 * 128 * 1024;  // hidden_states[-1]

    // [1] query projections: v1 = q @ W0^T  (3 tasks, ONE launch)
    {
        Task t[3] = {
            mk_task(context, 512, Wv0, 512, 512, v1v, 1024, nullptr, nullptr),
            mk_task(context, 512, Wa0, 512, 512, v1a, 1024, nullptr, nullptr),
            mk_task(context, 512, Wh0, 512, 512, v1h, 1024, nullptr, nullptr),
        };
        launch_tasks(128, 1024, t, 3);
    }
    // [2] round+permute activations (z=3, per-z sizes)
    {
        RPW w;
        w.src[0] = (const float4*)visual;  w.dst[0] = (float4*)vr; w.ng[0] = 1048576;
        w.src[1] = (const float4*)audio;   w.dst[1] = (float4*)ar; w.ng[1] = 1048576;
        w.src[2] = (const float4*)hstates; w.dst[2] = (float4*)hr; w.ng[2] = 131072;
        round_perm_tf32_z<<<dim3(4096, 1, 3), 256>>>(w);
    }
    // [3] round+permute weights (z=3)
    {
        RPW w;
        w.src[0] = (const float4*)Wv1; w.dst[0] = (float4*)w1v; w.ng[0] = 65536;
        w.src[1] = (const float4*)Wa1; w.dst[1] = (float4*)w1a; w.ng[1] = 65536;
        w.src[2] = (const float4*)Wh1; w.dst[2] = (float4*)w1h; w.ng[2] = 65536;
        round_perm_tf32_z<<<dim3(256, 1, 3), 256>>>(w);
    }
    // [4] fast score GEMMs: visual + audio + hidden, ONE launch (ncu slot)
    {
        STasks st;
        st.t[0] = { vr, w1v, v1v, Wv2, spv, 16384, 7, 127, 0 };
        st.t[1] = { ar, w1a, v1a, Wa2, spa, 16384, 7, 127, 0 };
        st.t[2] = { hr, w1h, v1h, Wh2, sph, 2048,  0, 127, 0 };
        mma_perm<<<dim3(8, 128, 3), 256>>>(st, 1024 / PKT);
    }

    // --- attention: softmax over partial scores + context accumulation ---
    attn2<<<dim3(128, 4), 256>>>(128, 8, 16384, spv, 128, 1,
                                 visual, 128 * 1024, 1024, ctxv, 1024);
    attn2<<<dim3(128, 4), 256>>>(128, 8, 16384, spa, 128, 1,
                                 audio, 128 * 1024, 1024, ctxa, 1024);
    attn2<<<dim3(128, 4), 256>>>(16, 8, 2048, sph, 1, 128,
                                 hstates, 1024, 128 * 1024, ctxh, 1024);

    // --- context stack (3 tasks) + Wc0 query projection (1 task): ONE launch ---
    {
        Task t[4] = {
            mk_task(ctxa,   1024, Wac, 1024, 1024, cstack + 0,    1536, bac, nullptr),
            mk_task(ctxv,   1024, Wvc, 1024, 1024, cstack + 512,  1536, bvc, nullptr),
            mk_task(ctxh,   1024, Whc, 1024, 1024, cstack + 1024, 1536, bhc, nullptr),
            mk_task(hidden, 1024, Wc0, 1024, 1024, v1c,           512,  nullptr, nullptr),
        };
        launch_tasks(128, 512, t, 4);
    }

    // --- v2c = cstack @ Wc1^T ---
    {
        Task t = mk_task(cstack, 512, Wc1, 512, 512, v2c, 512, nullptr, nullptr);
        launch_tasks(384, 512, &t, 1);
    }
    attn_ctx<<<128, 256>>>(3, 512, 512, v1c, v2c, 3 * 512, 512, Wc2,
                           cstack, 3 * 512, 512, out_fctx, 512);

    // --- LSTM gates: 3 K-segments accumulated in ONE launch ---
    {
        Task t = mk_task(out_fctx, 512, W_ih, 1536, 512, gates, 4096, b_ih, b_hh);
        t.seg[1].A = input;  t.seg[1].lda = 1024; t.seg[1].B = W_ih + 512; t.seg[1].ldb = 1536; t.seg[1].K = 1024;
        t.seg[2].A = hidden; t.seg[2].lda = 1024; t.seg[2].B = W_hh;       t.seg[2].ldb = 1024; t.seg[2].K = 1024;
        t.nseg = 3;
        launch_tasks(128, 4096, &t, 1);
    }

    lstm_cell<<<512, 256>>>(gates, cell, out_h, out_c);

    // --- logits = h_new @ W_out^T + b_out ---
    {
        Task t = mk_task(out_h, 1024, W_out, 1024, 1024, out_logits, 20000, b_out, nullptr);
        launch_tasks(128, 20000, &t, 1);
    }
}

// round 14
// speedup vs baseline: 1.0534x; 1.0484x over previous
#include <cuda_runtime.h>
#include <math.h>
#include <stdint.h>

// ---------------- scratch (no allocation allowed) ----------------
__device__ float g_spart_v[8 * 16384];      // partial scores, visual (nblk, b*128+t)
__device__ float g_spart_a[8 * 16384];      // partial scores, audio
__device__ float g_spart_h[8 * 2048];       // partial scores, hidden (nblk, l*128+b)
__device__ float g_v1v[128 * 1024];
__device__ float g_v1a[128 * 1024];
__device__ float g_v1h[128 * 1024];
__device__ float g_ctxv[128 * 1024];
__device__ float g_ctxa[128 * 1024];
__device__ float g_ctxh[128 * 1024];
__device__ float g_cstack[128 * 3 * 512];   // (b, slot, 512)
__device__ float g_v1c[128 * 512];
__device__ float g_v2c[128 * 3 * 512];
__device__ float g_gates[128 * 4096];
// tf32-RNA-rounded + k-permuted copies for the fast score GEMMs
__device__ float g_vr[16384 * 1024];
__device__ float g_ar[16384 * 1024];
__device__ float g_hr[2048 * 1024];
__device__ float g_w1v[1024 * 1024];
__device__ float g_w1a[1024 * 1024];
__device__ float g_w1h[1024 * 1024];

__device__ __forceinline__ unsigned cvt_tf32(float x) {
    unsigned r;
    asm("cvt.rna.tf32.f32 %0, %1;" : "=r"(r) : "f"(x));
    return r;
}
__device__ __forceinline__ float rna_tf32(float x) {
    return __uint_as_float(cvt_tf32(x));
}

__device__ __forceinline__ void cp_async16(unsigned smem_dst, const float* src, int bytes) {
    asm volatile("cp.async.cg.shared.global [%0], [%1], 16, %2;\n"
                 :: "r"(smem_dst), "l"(src), "r"(bytes));
}

// ---------------- tf32 RNA round + k-group permute -------------------
// For each 16-float group along k: out[4*(k&3)+(k>>2)] = rna(in[k]).
__global__ void round_perm_tf32(const float4* __restrict__ src,
                                float4* __restrict__ dst, int ngroups)
{
    int g = blockIdx.x * blockDim.x + threadIdx.x;
    if (g < ngroups) {
        const float4* s = src + (size_t)g * 4;
        float4 v0 = s[0], v1 = s[1], v2 = s[2], v3 = s[3];
        float4* d = dst + (size_t)g * 4;
        d[0] = make_float4(rna_tf32(v0.x), rna_tf32(v1.x), rna_tf32(v2.x), rna_tf32(v3.x));
        d[1] = make_float4(rna_tf32(v0.y), rna_tf32(v1.y), rna_tf32(v2.y), rna_tf32(v3.y));
        d[2] = make_float4(rna_tf32(v0.z), rna_tf32(v1.z), rna_tf32(v2.z), rna_tf32(v3.z));
        d[3] = make_float4(rna_tf32(v0.w), rna_tf32(v1.w), rna_tf32(v2.w), rna_tf32(v3.w));
    }
}

// batched variant: z indexes 3 (src,dst) pairs of equal size
struct RPW { const float4* src[3]; float4* dst[3]; };
__global__ void round_perm_tf32_z(RPW w, int ngroups)
{
    int g = blockIdx.x * blockDim.x + threadIdx.x;
    const float4* src = w.src[blockIdx.z];
    float4* dst = w.dst[blockIdx.z];
    if (g < ngroups) {
        const float4* s = src + (size_t)g * 4;
        float4 v0 = s[0], v1 = s[1], v2 = s[2], v3 = s[3];
        float4* d = dst + (size_t)g * 4;
        d[0] = make_float4(rna_tf32(v0.x), rna_tf32(v1.x), rna_tf32(v2.x), rna_tf32(v3.x));
        d[1] = make_float4(rna_tf32(v0.y), rna_tf32(v1.y), rna_tf32(v2.y), rna_tf32(v3.y));
        d[2] = make_float4(rna_tf32(v0.z), rna_tf32(v1.z), rna_tf32(v2.z), rna_tf32(v3.z));
        d[3] = make_float4(rna_tf32(v0.w), rna_tf32(v1.w), rna_tf32(v2.w), rna_tf32(v3.w));
    }
}

// =======================================================================
// FAST score GEMM on pre-rounded, k-permuted inputs (R9 champion version).
// =======================================================================
#define PKT 16

struct STask {
    const float* A;
    const float* B;
    const float* v1;
    const float* w2;
    float* spart;
    int M;
    int shift;
    int mask;
    int pad;
};
struct STasks { STask t[3]; };

__global__ __launch_bounds__(256, 2) void mma_perm(STasks ts, int nk)
{
    __shared__ float As[2][128][PKT];
    __shared__ float Bs[2][128][PKT];
    __shared__ float s_ws[4][128];

    const STask& tk = ts.t[blockIdx.z];
    const int bm = blockIdx.y * 128;
    if (bm >= tk.M) return;
    const int bn = blockIdx.x * 128;

    const int tid  = threadIdx.x;
    const int wid  = tid >> 5, lane = tid & 31;
    const int wm   = wid >> 2;
    const int wn   = wid & 3;
    const int gq   = lane >> 2;
    const int tq   = lane & 3;

    const float* A = tk.A + (size_t)bm * 1024;
    const float* B = tk.B + (size_t)bn * 1024;

    float acc[4][4][4];
#pragma unroll
    for (int i = 0; i < 4; i++)
#pragma unroll
        for (int j = 0; j < 4; j++)
#pragma unroll
            for (int v = 0; v < 4; v++) acc[i][j][v] = 0.0f;

    const int srow0 = tid >> 2, sch0 = (tid & 3) << 2;
    const int srow1 = (tid + 256) >> 2, sch1 = sch0;

    auto prefetch = [&](int st, int k0) {
        cp_async16((unsigned)__cvta_generic_to_shared(&As[st][srow0][sch0]),
                   A + (size_t)srow0 * 1024 + k0 + sch0, 16);
        cp_async16((unsigned)__cvta_generic_to_shared(&As[st][srow1][sch1]),
                   A + (size_t)srow1 * 1024 + k0 + sch1, 16);
        cp_async16((unsigned)__cvta_generic_to_shared(&Bs[st][srow0][sch0]),
                   B + (size_t)srow0 * 1024 + k0 + sch0, 16);
        cp_async16((unsigned)__cvta_generic_to_shared(&Bs[st][srow1][sch1]),
                   B + (size_t)srow1 * 1024 + k0 + sch1, 16);
    };

    prefetch(0, 0);
    asm volatile("cp.async.commit_group;\n" ::: "memory");

    for (int it = 0; it < nk; it++) {
        asm volatile("cp.async.wait_group 0;\n" ::: "memory");
        __syncthreads();
        if (it + 1 < nk) {
            prefetch((it + 1) & 1, (it + 1) * PKT);
            asm volatile("cp.async.commit_group;\n" ::: "memory");
        }
        const int s = it & 1;

        float4 bf[4];
#pragma unroll
        for (int nf = 0; nf < 4; nf++)
            bf[nf] = *reinterpret_cast<const float4*>(&Bs[s][wn * 32 + nf * 8 + gq][tq * 4]);

#pragma unroll
        for (int mf = 0; mf < 4; mf++) {
            const int mr = wm * 64 + mf * 16;
            float4 alo = *reinterpret_cast<const float4*>(&As[s][mr + gq    ][tq * 4]);
            float4 ahi = *reinterpret_cast<const float4*>(&As[s][mr + gq + 8][tq * 4]);
#pragma unroll
            for (int nf = 0; nf < 4; nf++) {
                float* c = acc[mf][nf];
                asm volatile(
                    "mma.sync.aligned.m16n8k8.row.col.f32.tf32.tf32.f32 "
                    "{%0,%1,%2,%3}, {%4,%5,%6,%7}, {%8,%9}, {%0,%1,%2,%3};\n"
                    : "+f"(c[0]), "+f"(c[1]), "+f"(c[2]), "+f"(c[3])
                    : "r"(__float_as_uint(alo.x)), "r"(__float_as_uint(ahi.x)),
                      "r"(__float_as_uint(alo.y)), "r"(__float_as_uint(ahi.y)),
                      "r"(__float_as_uint(bf[nf].x)), "r"(__float_as_uint(bf[nf].y)));
            }
#pragma unroll
            for (int nf = 0; nf < 4; nf++) {
                float* c = acc[mf][nf];
                asm volatile(
                    "mma.sync.aligned.m16n8k8.row.col.f32.tf32.tf32.f32 "
                    "{%0,%1,%2,%3}, {%4,%5,%6,%7}, {%8,%9}, {%0,%1,%2,%3};\n"
                    : "+f"(c[0]), "+f"(c[1]), "+f"(c[2]), "+f"(c[3])
                    : "r"(__float_as_uint(alo.z)), "r"(__float_as_uint(ahi.z)),
                      "r"(__float_as_uint(alo.w)), "r"(__float_as_uint(ahi.w)),
                      "r"(__float_as_uint(bf[nf].z)), "r"(__float_as_uint(bf[nf].w)));
            }
        }
    }

    const float* v1 = tk.v1;
    const float* w2 = tk.w2;
    const int shift = tk.shift, mask = tk.mask;
#pragma unroll
    for (int mf = 0; mf < 4; mf++) {
        const int row0 = bm + wm * 64 + mf * 16 + gq;
        const int row1 = row0 + 8;
        const size_t v1b0 = (size_t)((row0 >> shift) & mask) * 1024;
        const size_t v1b1 = (size_t)((row1 >> shift) & mask) * 1024;
        float s0 = 0.f, s1 = 0.f;
#pragma unroll
        for (int nf = 0; nf < 4; nf++) {
            const int col = bn + wn * 32 + nf * 8 + tq * 2;
            const float w0 = w2[col], w1 = w2[col + 1];
            s0 += tanhf(acc[mf][nf][0] + v1[v1b0 + col])     * w0
                + tanhf(acc[mf][nf][1] + v1[v1b0 + col + 1]) * w1;
            s1 += tanhf(acc[mf][nf][2] + v1[v1b1 + col])     * w0
                + tanhf(acc[mf][nf][3] + v1[v1b1 + col + 1]) * w1;
        }
        s0 += __shfl_xor_sync(0xffffffffu, s0, 1);
        s0 += __shfl_xor_sync(0xffffffffu, s0, 2);
        s1 += __shfl_xor_sync(0xffffffffu, s1, 1);
        s1 += __shfl_xor_sync(0xffffffffu, s1, 2);
        if (tq == 0) {
            s_ws[wn][wm * 64 + mf * 16 + gq]     = s0;
            s_ws[wn][wm * 64 + mf * 16 + gq + 8] = s1;
        }
    }
    __syncthreads();
    for (int i = tid; i < 128; i += 256) {
        float v = s_ws[0][i] + s_ws[1][i] + s_ws[2][i] + s_ws[3][i];
        tk.spart[(size_t)blockIdx.x * tk.M + bm + i] = v;
    }
}

// =======================================================================
// General mma.sync TF32 GEMM (all non-score GEMMs) — unchanged.
// =======================================================================
#define BM 128
#define BN 128
#define BK 16
#define LDSS 20

struct Seg {
    const float* A;
    const float* B;
    long long lda;
    long long ldb;
    int K;
    int pad;
};
struct Task {
    Seg seg[3];
    float* C;
    const float* bias1;
    const float* bias2;
    long long ldc;
    int nseg;
    int pad;
};
struct Tasks4 { Task t[4]; };

__global__ __launch_bounds__(256, 2) void mma_tn_g(int M, int N, Tasks4 ts)
{
    __shared__ float As[2][BM][LDSS];
    __shared__ float Bs[2][BN][LDSS];

    const Task& tk = ts.t[blockIdx.z];

    const int tid  = threadIdx.x;
    const int wid  = tid >> 5, lane = tid & 31;
    const int wm   = wid >> 2;
    const int wn   = wid & 3;
    const int gq   = lane >> 2;
    const int tq   = lane & 3;

    const int bm = blockIdx.y * BM;
    const int bn = blockIdx.x * BN;

    const int lr = tid >> 2;
    const int lc = (tid & 3) << 2;

    float acc[4][4][4];
#pragma unroll
    for (int i = 0; i < 4; i++)
#pragma unroll
        for (int j = 0; j < 4; j++)
#pragma unroll
            for (int v = 0; v < 4; v++) acc[i][j][v] = 0.0f;

    int total_nk = 0;
    for (int i = 0; i < tk.nseg; i++) total_nk += tk.seg[i].K >> 4;

    auto prefetch = [&](int st, int si, int k0) {
        const float* Aseg = tk.seg[si].A;
        const float* Bseg = tk.seg[si].B;
        const long long lda = tk.seg[si].lda;
        const long long ldb = tk.seg[si].ldb;
#pragma unroll
        for (int part = 0; part < 2; part++) {
            int r = lr + part * 64;
            const float* asrc = Aseg + (size_t)(bm + r) * lda + k0 + lc;
            unsigned ad = (unsigned)__cvta_generic_to_shared(&As[st][r][lc]);
            cp_async16(ad, asrc, 16);
            int gn = bn + r;
            int ok = (gn < N);
            const float* bsrc = Bseg + (size_t)(ok ? gn : 0) * ldb + k0 + lc;
            unsigned bd = (unsigned)__cvta_generic_to_shared(&Bs[st][r][lc]);
            cp_async16(bd, bsrc, ok ? 16 : 0);
        }
    };

    prefetch(0, 0, 0);
    asm volatile("cp.async.commit_group;\n" ::: "memory");
    int psi = 0, pk0 = BK;
    if (pk0 >= tk.seg[0].K) { psi = 1; pk0 = 0; }

    for (int it = 0; it < total_nk; it++) {
        asm volatile("cp.async.wait_group 0;\n" ::: "memory");
        __syncthreads();
        if (it + 1 < total_nk) {
            prefetch((it + 1) & 1, psi, pk0);
            asm volatile("cp.async.commit_group;\n" ::: "memory");
            pk0 += BK;
            if (pk0 >= tk.seg[psi].K) { psi = (psi < 2) ? psi + 1 : psi; pk0 = 0; }
        }
        const int s = it & 1;

#pragma unroll
        for (int kk = 0; kk < BK; kk += 8) {
            unsigned af[4][4], bfr[4][2];
#pragma unroll
            for (int mf = 0; mf < 4; mf++) {
                const int mr = wm * 64 + mf * 16;
                af[mf][0] = cvt_tf32(As[s][mr + gq    ][kk + tq    ]);
                af[mf][1] = cvt_tf32(As[s][mr + gq + 8][kk + tq    ]);
                af[mf][2] = cvt_tf32(As[s][mr + gq    ][kk + tq + 4]);
                af[mf][3] = cvt_tf32(As[s][mr + gq + 8][kk + tq + 4]);
            }
#pragma unroll
            for (int nf = 0; nf < 4; nf++) {
                const int nr = wn * 32 + nf * 8;
                bfr[nf][0] = cvt_tf32(Bs[s][nr + gq][kk + tq    ]);
                bfr[nf][1] = cvt_tf32(Bs[s][nr + gq][kk + tq + 4]);
            }
#pragma unroll
            for (int mf = 0; mf < 4; mf++)
#pragma unroll
                for (int nf = 0; nf < 4; nf++) {
                    float* c = acc[mf][nf];
                    asm volatile(
                        "mma.sync.aligned.m16n8k8.row.col.f32.tf32.tf32.f32 "
                        "{%0,%1,%2,%3}, {%4,%5,%6,%7}, {%8,%9}, {%0,%1,%2,%3};\n"
                        : "+f"(c[0]), "+f"(c[1]), "+f"(c[2]), "+f"(c[3])
                        : "r"(af[mf][0]), "r"(af[mf][1]), "r"(af[mf][2]), "r"(af[mf][3]),
                          "r"(bfr[nf][0]), "r"(bfr[nf][1]));
                }
        }
    }

    float* C = tk.C;
    const long long ldc = tk.ldc;
    const float* b1 = tk.bias1;
    const float* b2 = tk.bias2;
#pragma unroll
    for (int mf = 0; mf < 4; mf++) {
        const int row = bm + wm * 64 + mf * 16 + gq;
#pragma unroll
        for (int nf = 0; nf < 4; nf++) {
            const int col = bn + wn * 32 + nf * 8 + tq * 2;
            if (col < N) {
                float2 v0 = make_float2(acc[mf][nf][0], acc[mf][nf][1]);
                float2 v1x = make_float2(acc[mf][nf][2], acc[mf][nf][3]);
                if (b1) {
                    float bx = b1[col], by = b1[col + 1];
                    v0.x += bx; v0.y += by; v1x.x += bx; v1x.y += by;
                }
                if (b2) {
                    float bx = b2[col], by = b2[col + 1];
                    v0.x += bx; v0.y += by; v1x.x += bx; v1x.y += by;
                }
                size_t i0 = (size_t)row * ldc + col;
                size_t i1 = (size_t)(row + 8) * ldc + col;
                *reinterpret_cast<float2*>(&C[i0]) = v0;
                *reinterpret_cast<float2*>(&C[i1]) = v1x;
            }
        }
    }
}

// ---------------- attention part 2, z-batched (3 independent tasks) ------
// grid (B, D/256, 3), 256 threads; one d per thread, 4-way t accumulation.
struct ATask {
    const float* spart;
    const float* vec2;
    float* out;
    int T;
    int nb;
    int Msp;
    int sp_sb;
    int sp_st;
    int pad;
    long long vv_sb;
    long long vv_st;
    long long out_sb;
};
struct ATasks { ATask t[3]; };

__global__ __launch_bounds__(256) void attn2z(ATasks ts)
{
    __shared__ float s_score[128];
    __shared__ float s_red[256];

    const ATask& a = ts.t[blockIdx.z];
    const int T = a.T, nb = a.nb, Msp = a.Msp;
    const int b = blockIdx.x;
    const int tid = threadIdx.x;

    for (int t = tid; t < T; t += 256) {
        float s = 0.f;
        const float* p = a.spart + (size_t)b * a.sp_sb + (size_t)t * a.sp_st;
#pragma unroll
        for (int k = 0; k < 8; k++)
            if (k < nb) s += p[(size_t)k * Msp];
        s_score[t] = s;
    }
    __syncthreads();

    float m = -1e30f;
    for (int t = tid; t < T; t += 256) m = fmaxf(m, s_score[t]);
    s_red[tid] = m;
    __syncthreads();
    for (int s = 128; s > 0; s >>= 1) {
        if (tid < s) s_red[tid] = fmaxf(s_red[tid], s_red[tid + s]);
        __syncthreads();
    }
    const float mx = s_red[0];
    __syncthreads();
    float lsum = 0.f;
    for (int t = tid; t < T; t += 256) {
        float e = expf(s_score[t] - mx);
        s_score[t] = e;
        lsum += e;
    }
    s_red[tid] = lsum;
    __syncthreads();
    for (int s = 128; s > 0; s >>= 1) {
        if (tid < s) s_red[tid] += s_red[tid + s];
        __syncthreads();
    }
    const float inv = 1.0f / s_red[0];

    const int d = blockIdx.y * 256 + tid;
    const float* base = a.vec2 + (size_t)b * a.vv_sb + d;
    const long long vst = a.vv_st;
    float a0 = 0.f, a1 = 0.f, a2 = 0.f, a3 = 0.f;
    for (int t = 0; t < T; t += 4) {
        a0 += s_score[t    ] * base[(size_t)(t    ) * vst];
        a1 += s_score[t + 1] * base[(size_t)(t + 1) * vst];
        a2 += s_score[t + 2] * base[(size_t)(t + 2) * vst];
        a3 += s_score[t + 3] * base[(size_t)(t + 3) * vst];
    }
    a.out[(size_t)b * a.out_sb + d] = ((a0 + a1) + (a2 + a3)) * inv;
}

// ---------------- fused attention (tiny final T=3) ------
__global__ __launch_bounds__(256) void attn_ctx(
    int T, int E, int D,
    const float* __restrict__ v1,
    const float* __restrict__ v2, long long v2_sb, long long v2_st,
    const float* __restrict__ w2,
    const float* __restrict__ vec2, long long vv_sb, long long vv_st,
    float* __restrict__ out, long long out_sb)
{
    __shared__ float s_v1[1024];
    __shared__ float s_w2[1024];
    __shared__ float s_score[128];
    __shared__ float s_red[256];

    const int b = blockIdx.x;
    const int tid = threadIdx.x;
    for (int j = tid; j < E; j += 256) {
        s_v1[j] = v1[(size_t)b * E + j];
        s_w2[j] = w2[j];
    }
    __syncthreads();

    const int warp = tid >> 5, lane = tid & 31;
    for (int t = warp; t < T; t += 8) {
        const float* p = v2 + (long long)b * v2_sb + (long long)t * v2_st;
        float sum = 0.f;
        for (int j = lane; j < E; j += 32)
            sum += tanhf(s_v1[j] + p[j]) * s_w2[j];
#pragma unroll
        for (int o = 16; o > 0; o >>= 1) sum += __shfl_xor_sync(0xffffffffu, sum, o);
        if (lane == 0) s_score[t] = sum;
    }
    __syncthreads();

    float m = -1e30f;
    for (int t = tid; t < T; t += 256) m = fmaxf(m, s_score[t]);
    s_red[tid] = m;
    __syncthreads();
    for (int s = 128; s > 0; s >>= 1) {
        if (tid < s) s_red[tid] = fmaxf(s_red[tid], s_red[tid + s]);
        __syncthreads();
    }
    const float mx = s_red[0];
    __syncthreads();
    float lsum = 0.f;
    for (int t = tid; t < T; t += 256) {
        float e = expf(s_score[t] - mx);
        s_score[t] = e;
        lsum += e;
    }
    s_red[tid] = lsum;
    __syncthreads();
    for (int s = 128; s > 0; s >>= 1) {
        if (tid < s) s_red[tid] += s_red[tid + s];
        __syncthreads();
    }
    const float inv = 1.0f / s_red[0];

    for (int d = tid; d < D; d += 256) {
        const float* base = vec2 + (long long)b * vv_sb + d;
        float accd = 0.f;
        for (int t = 0; t < T; t++)
            accd += s_score[t] * base[(long long)t * vv_st];
        out[(long long)b * out_sb + d] = accd * inv;
    }
}

// ---------------- LSTM cell elementwise ----------------
__global__ void lstm_cell(const float* __restrict__ gates,
                          const float* __restrict__ cell,
                          float* __restrict__ h_out,
                          float* __restrict__ c_out)
{
    int idx = blockIdx.x * blockDim.x + threadIdx.x;
    int b = idx >> 10, j = idx & 1023;
    const float* g = gates + (size_t)b * 4096;
    float i_ = 1.f / (1.f + expf(-g[j]));
    float f_ = 1.f / (1.f + expf(-g[1024 + j]));
    float gg = tanhf(g[2048 + j]);
    float o_ = 1.f / (1.f + expf(-g[3072 + j]));
    float c = f_ * cell[idx] + i_ * gg;
    float h = o_ * tanhf(c);
    c_out[idx] = c;
    h_out[idx] = h;
}

// ---------------- host-side task builders ----------------
static Task mk_task(const float* A, long long lda, const float* B, long long ldb,
                    int K, float* C, long long ldc,
                    const float* b1, const float* b2)
{
    Task t;
    for (int i = 0; i < 3; i++) { t.seg[i].A = A; t.seg[i].B = B; t.seg[i].lda = lda;
                                  t.seg[i].ldb = ldb; t.seg[i].K = K; t.seg[i].pad = 0; }
    t.nseg = 1; t.C = C; t.ldc = ldc; t.bias1 = b1; t.bias2 = b2; t.pad = 0;
    return t;
}

static void launch_tasks(int M, int N, const Task* tasks, int nz)
{
    Tasks4 ts;
    for (int i = 0; i < 4; i++) ts.t[i] = tasks[i < nz ? i : 0];
    dim3 grid((N + BN - 1) / BN, M / BM, nz);
    mma_tn_g<<<grid, 256>>>(M, N, ts);
}

extern "C" void kernel_launch(void* const* d_in, const int* in_sizes, int n_in,
                              void* d_out, int out_size)
{
    const float* input   = (const float*)d_in[0];   // [128,1,1024]
    const float* visual  = (const float*)d_in[1];   // [128,128,1024]
    const float* audio   = (const float*)d_in[2];   // [128,128,1024]
    const float* hstates = (const float*)d_in[3];   // [16,128,1024]
    const float* cell    = (const float*)d_in[4];   // [128,1024]
    const float* context = (const float*)d_in[5];   // [128,1,512]
    const float* Wv0 = (const float*)d_in[6];
    const float* Wv1 = (const float*)d_in[7];
    const float* Wv2 = (const float*)d_in[8];
    const float* Wa0 = (const float*)d_in[9];
    const float* Wa1 = (const float*)d_in[10];
    const float* Wa2 = (const float*)d_in[11];
    const float* Wh0 = (const float*)d_in[12];
    const float* Wh1 = (const float*)d_in[13];
    const float* Wh2 = (const float*)d_in[14];
    const float* Wc0 = (const float*)d_in[15];
    const float* Wc1 = (const float*)d_in[16];
    const float* Wc2 = (const float*)d_in[17];
    const float* Wac = (const float*)d_in[18];
    const float* bac = (const float*)d_in[19];
    const float* Wvc = (const float*)d_in[20];
    const float* bvc = (const float*)d_in[21];
    const float* Whc = (const float*)d_in[22];
    const float* bhc = (const float*)d_in[23];
    const float* W_ih = (const float*)d_in[24];     // [4096,1536]
    const float* W_hh = (const float*)d_in[25];     // [4096,1024]
    const float* b_ih = (const float*)d_in[26];
    const float* b_hh = (const float*)d_in[27];
    const float* W_out = (const float*)d_in[28];    // [20000,1024]
    const float* b_out = (const float*)d_in[29];

    float* out = (float*)d_out;
    float* out_logits = out;
    float* out_h      = out + 2560000;
    float* out_c      = out + 2560000 + 131072;
    float* out_fctx   = out + 2560000 + 131072 + 131072;

    float *spv, *spa, *sph, *v1v, *v1a, *v1h, *ctxv, *ctxa, *ctxh,
          *cstack, *v1c, *v2c, *gates, *vr, *ar, *hr, *w1v, *w1a, *w1h;
    cudaGetSymbolAddress((void**)&spv, g_spart_v);
    cudaGetSymbolAddress((void**)&spa, g_spart_a);
    cudaGetSymbolAddress((void**)&sph, g_spart_h);
    cudaGetSymbolAddress((void**)&v1v, g_v1v);
    cudaGetSymbolAddress((void**)&v1a, g_v1a);
    cudaGetSymbolAddress((void**)&v1h, g_v1h);
    cudaGetSymbolAddress((void**)&ctxv, g_ctxv);
    cudaGetSymbolAddress((void**)&ctxa, g_ctxa);
    cudaGetSymbolAddress((void**)&ctxh, g_ctxh);
    cudaGetSymbolAddress((void**)&cstack, g_cstack);
    cudaGetSymbolAddress((void**)&v1c, g_v1c);
    cudaGetSymbolAddress((void**)&v2c, g_v2c);
    cudaGetSymbolAddress((void**)&gates, g_gates);
    cudaGetSymbolAddress((void**)&vr, g_vr);
    cudaGetSymbolAddress((void**)&ar, g_ar);
    cudaGetSymbolAddress((void**)&hr, g_hr);
    cudaGetSymbolAddress((void**)&w1v, g_w1v);
    cudaGetSymbolAddress((void**)&w1a, g_w1a);
    cudaGetSymbolAddress((void**)&w1h, g_w1h);

    const float* hidden = hstates + (size_t)15 * 128 * 1024;  // hidden_states[-1]

    // [1..3] round+permute activations (R9 champion ordering)
    round_perm_tf32<<<4096, 256>>>((const float4*)visual, (float4*)vr, 1048576);
    round_perm_tf32<<<4096, 256>>>((const float4*)audio, (float4*)ar, 1048576);
    round_perm_tf32<<<512, 256>>>((const float4*)hstates, (float4*)hr, 131072);
    // [4] round+permute the 3 weight matrices, batched (z=3)
    {
        RPW w;
        w.src[0] = (const float4*)Wv1; w.dst[0] = (float4*)w1v;
        w.src[1] = (const float4*)Wa1; w.dst[1] = (float4*)w1a;
        w.src[2] = (const float4*)Wh1; w.dst[2] = (float4*)w1h;
        round_perm_tf32_z<<<dim3(256, 1, 3), 256>>>(w, 65536);
    }
    // [5] query projections: v1 = q @ W0^T  (3 tasks, ONE launch)
    {
        Task t[3] = {
            mk_task(context, 512, Wv0, 512, 512, v1v, 1024, nullptr, nullptr),
            mk_task(context, 512, Wa0, 512, 512, v1a, 1024, nullptr, nullptr),
            mk_task(context, 512, Wh0, 512, 512, v1h, 1024, nullptr, nullptr),
        };
        launch_tasks(128, 1024, t, 3);
    }
    // [6] fast score GEMMs: visual + audio + hidden, ONE launch
    {
        STasks st;
        st.t[0] = { vr, w1v, v1v, Wv2, spv, 16384, 7, 127, 0 };
        st.t[1] = { ar, w1a, v1a, Wa2, spa, 16384, 7, 127, 0 };
        st.t[2] = { hr, w1h, v1h, Wh2, sph, 2048,  0, 127, 0 };
        mma_perm<<<dim3(8, 128, 3), 256>>>(st, 1024 / PKT);
    }

    // [7] attention part 2: visual + audio + hidden in ONE z=3 launch
    {
        ATasks at;
        at.t[0] = { spv, visual,  ctxv, 128, 8, 16384, 128, 1,   0, 128 * 1024, 1024,       1024 };
        at.t[1] = { spa, audio,   ctxa, 128, 8, 16384, 128, 1,   0, 128 * 1024, 1024,       1024 };
        at.t[2] = { sph, hstates, ctxh, 16,  8, 2048,  1,   128, 0, 1024,       128 * 1024, 1024 };
        attn2z<<<dim3(128, 4, 3), 256>>>(at);
    }

    // --- context stack (3 tasks) + Wc0 query projection (1 task): ONE launch ---
    {
        Task t[4] = {
            mk_task(ctxa,   1024, Wac, 1024, 1024, cstack + 0,    1536, bac, nullptr),
            mk_task(ctxv,   1024, Wvc, 1024, 1024, cstack + 512,  1536, bvc, nullptr),
            mk_task(ctxh,   1024, Whc, 1024, 1024, cstack + 1024, 1536, bhc, nullptr),
            mk_task(hidden, 1024, Wc0, 1024, 1024, v1c,           512,  nullptr, nullptr),
        };
        launch_tasks(128, 512, t, 4);
    }

    // --- v2c = cstack @ Wc1^T ---
    {
        Task t = mk_task(cstack, 512, Wc1, 512, 512, v2c, 512, nullptr, nullptr);
        launch_tasks(384, 512, &t, 1);
    }
    attn_ctx<<<128, 256>>>(3, 512, 512, v1c, v2c, 3 * 512, 512, Wc2,
                           cstack, 3 * 512, 512, out_fctx, 512);

    // --- LSTM gates: 3 K-segments accumulated in ONE launch ---
    {
        Task t = mk_task(out_fctx, 512, W_ih, 1536, 512, gates, 4096, b_ih, b_hh);
        t.seg[1].A = input;  t.seg[1].lda = 1024; t.seg[1].B = W_ih + 512; t.seg[1].ldb = 1536; t.seg[1].K = 1024;
        t.seg[2].A = hidden; t.seg[2].lda = 1024; t.seg[2].B = W_hh;       t.seg[2].ldb = 1024; t.seg[2].K = 1024;
        t.nseg = 3;
        launch_tasks(128, 4096, &t, 1);
    }

    lstm_cell<<<512, 256>>>(gates, cell, out_h, out_c);

    // --- logits = h_new @ W_out^T + b_out ---
    {
        Task t = mk_task(out_h, 1024, W_out, 1024, 1024, out_logits, 20000, b_out, nullptr);
        launch_tasks(128, 20000, &t, 1);
    }
}

// round 17
// speedup vs baseline: 1.1882x; 1.1281x over previous
#include <cuda_runtime.h>
#include <math.h>
#include <stdint.h>

// ---------------- scratch (no allocation allowed) ----------------
__device__ float g_spart_v[8 * 16384];      // partial scores, visual (nblk, b*128+t)
__device__ float g_spart_a[8 * 16384];      // partial scores, audio
__device__ float g_spart_h[8 * 2048];       // partial scores, hidden (nblk, l*128+b)
__device__ float g_v1v[128 * 1024];
__device__ float g_v1a[128 * 1024];
__device__ float g_v1h[128 * 1024];
__device__ float g_ctxv[128 * 1024];
__device__ float g_ctxa[128 * 1024];
__device__ float g_ctxh[128 * 1024];
__device__ float g_cstack[128 * 3 * 512];   // (b, slot, 512)
__device__ float g_v1c[128 * 512];
__device__ float g_v2c[128 * 3 * 512];
__device__ float g_gates0[128 * 4096];
__device__ float g_gates1[128 * 4096];
__device__ float g_gates2[128 * 4096];
// tf32-RNA-rounded + k-permuted copies for the fast score GEMMs
__device__ float g_vr[16384 * 1024];
__device__ float g_ar[16384 * 1024];
__device__ float g_hr[2048 * 1024];
__device__ float g_w1v[1024 * 1024];
__device__ float g_w1a[1024 * 1024];
__device__ float g_w1h[1024 * 1024];

__device__ __forceinline__ unsigned cvt_tf32(float x) {
    unsigned r;
    asm("cvt.rna.tf32.f32 %0, %1;" : "=r"(r) : "f"(x));
    return r;
}
__device__ __forceinline__ float rna_tf32(float x) {
    return __uint_as_float(cvt_tf32(x));
}

__device__ __forceinline__ void cp_async16(unsigned smem_dst, const float* src, int bytes) {
    asm volatile("cp.async.cg.shared.global [%0], [%1], 16, %2;\n"
                 :: "r"(smem_dst), "l"(src), "r"(bytes));
}

// ---------------- tf32 RNA round + k-group permute -------------------
__global__ void round_perm_tf32(const float4* __restrict__ src,
                                float4* __restrict__ dst, int ngroups)
{
    int g = blockIdx.x * blockDim.x + threadIdx.x;
    if (g < ngroups) {
        const float4* s = src + (size_t)g * 4;
        float4 v0 = s[0], v1 = s[1], v2 = s[2], v3 = s[3];
        float4* d = dst + (size_t)g * 4;
        d[0] = make_float4(rna_tf32(v0.x), rna_tf32(v1.x), rna_tf32(v2.x), rna_tf32(v3.x));
        d[1] = make_float4(rna_tf32(v0.y), rna_tf32(v1.y), rna_tf32(v2.y), rna_tf32(v3.y));
        d[2] = make_float4(rna_tf32(v0.z), rna_tf32(v1.z), rna_tf32(v2.z), rna_tf32(v3.z));
        d[3] = make_float4(rna_tf32(v0.w), rna_tf32(v1.w), rna_tf32(v2.w), rna_tf32(v3.w));
    }
}

struct RPW { const float4* src[3]; float4* dst[3]; };
__global__ void round_perm_tf32_z(RPW w, int ngroups)
{
    int g = blockIdx.x * blockDim.x + threadIdx.x;
    const float4* src = w.src[blockIdx.z];
    float4* dst = w.dst[blockIdx.z];
    if (g < ngroups) {
        const float4* s = src + (size_t)g * 4;
        float4 v0 = s[0], v1 = s[1], v2 = s[2], v3 = s[3];
        float4* d = dst + (size_t)g * 4;
        d[0] = make_float4(rna_tf32(v0.x), rna_tf32(v1.x), rna_tf32(v2.x), rna_tf32(v3.x));
        d[1] = make_float4(rna_tf32(v0.y), rna_tf32(v1.y), rna_tf32(v2.y), rna_tf32(v3.y));
        d[2] = make_float4(rna_tf32(v0.z), rna_tf32(v1.z), rna_tf32(v2.z), rna_tf32(v3.z));
        d[3] = make_float4(rna_tf32(v0.w), rna_tf32(v1.w), rna_tf32(v2.w), rna_tf32(v3.w));
    }
}

// =======================================================================
// FAST score GEMM on pre-rounded, k-permuted inputs (R9 champion, frozen).
// =======================================================================
#define PKT 16

struct STask {
    const float* A;
    const float* B;
    const float* v1;
    const float* w2;
    float* spart;
    int M;
    int shift;
    int mask;
    int pad;
};
struct STasks { STask t[3]; };

__global__ __launch_bounds__(256, 2) void mma_perm(STasks ts, int nk)
{
    __shared__ float As[2][128][PKT];
    __shared__ float Bs[2][128][PKT];
    __shared__ float s_ws[4][128];

    const STask& tk = ts.t[blockIdx.z];
    const int bm = blockIdx.y * 128;
    if (bm >= tk.M) return;
    const int bn = blockIdx.x * 128;

    const int tid  = threadIdx.x;
    const int wid  = tid >> 5, lane = tid & 31;
    const int wm   = wid >> 2;
    const int wn   = wid & 3;
    const int gq   = lane >> 2;
    const int tq   = lane & 3;

    const float* A = tk.A + (size_t)bm * 1024;
    const float* B = tk.B + (size_t)bn * 1024;

    float acc[4][4][4];
#pragma unroll
    for (int i = 0; i < 4; i++)
#pragma unroll
        for (int j = 0; j < 4; j++)
#pragma unroll
            for (int v = 0; v < 4; v++) acc[i][j][v] = 0.0f;

    const int srow0 = tid >> 2, sch0 = (tid & 3) << 2;
    const int srow1 = (tid + 256) >> 2, sch1 = sch0;

    auto prefetch = [&](int st, int k0) {
        cp_async16((unsigned)__cvta_generic_to_shared(&As[st][srow0][sch0]),
                   A + (size_t)srow0 * 1024 + k0 + sch0, 16);
        cp_async16((unsigned)__cvta_generic_to_shared(&As[st][srow1][sch1]),
                   A + (size_t)srow1 * 1024 + k0 + sch1, 16);
        cp_async16((unsigned)__cvta_generic_to_shared(&Bs[st][srow0][sch0]),
                   B + (size_t)srow0 * 1024 + k0 + sch0, 16);
        cp_async16((unsigned)__cvta_generic_to_shared(&Bs[st][srow1][sch1]),
                   B + (size_t)srow1 * 1024 + k0 + sch1, 16);
    };

    prefetch(0, 0);
    asm volatile("cp.async.commit_group;\n" ::: "memory");

    for (int it = 0; it < nk; it++) {
        asm volatile("cp.async.wait_group 0;\n" ::: "memory");
        __syncthreads();
        if (it + 1 < nk) {
            prefetch((it + 1) & 1, (it + 1) * PKT);
            asm volatile("cp.async.commit_group;\n" ::: "memory");
        }
        const int s = it & 1;

        float4 bf[4];
#pragma unroll
        for (int nf = 0; nf < 4; nf++)
            bf[nf] = *reinterpret_cast<const float4*>(&Bs[s][wn * 32 + nf * 8 + gq][tq * 4]);

#pragma unroll
        for (int mf = 0; mf < 4; mf++) {
            const int mr = wm * 64 + mf * 16;
            float4 alo = *reinterpret_cast<const float4*>(&As[s][mr + gq    ][tq * 4]);
            float4 ahi = *reinterpret_cast<const float4*>(&As[s][mr + gq + 8][tq * 4]);
#pragma unroll
            for (int nf = 0; nf < 4; nf++) {
                float* c = acc[mf][nf];
                asm volatile(
                    "mma.sync.aligned.m16n8k8.row.col.f32.tf32.tf32.f32 "
                    "{%0,%1,%2,%3}, {%4,%5,%6,%7}, {%8,%9}, {%0,%1,%2,%3};\n"
                    : "+f"(c[0]), "+f"(c[1]), "+f"(c[2]), "+f"(c[3])
                    : "r"(__float_as_uint(alo.x)), "r"(__float_as_uint(ahi.x)),
                      "r"(__float_as_uint(alo.y)), "r"(__float_as_uint(ahi.y)),
                      "r"(__float_as_uint(bf[nf].x)), "r"(__float_as_uint(bf[nf].y)));
            }
#pragma unroll
            for (int nf = 0; nf < 4; nf++) {
                float* c = acc[mf][nf];
                asm volatile(
                    "mma.sync.aligned.m16n8k8.row.col.f32.tf32.tf32.f32 "
                    "{%0,%1,%2,%3}, {%4,%5,%6,%7}, {%8,%9}, {%0,%1,%2,%3};\n"
                    : "+f"(c[0]), "+f"(c[1]), "+f"(c[2]), "+f"(c[3])
                    : "r"(__float_as_uint(alo.z)), "r"(__float_as_uint(ahi.z)),
                      "r"(__float_as_uint(alo.w)), "r"(__float_as_uint(ahi.w)),
                      "r"(__float_as_uint(bf[nf].z)), "r"(__float_as_uint(bf[nf].w)));
            }
        }
    }

    const float* v1 = tk.v1;
    const float* w2 = tk.w2;
    const int shift = tk.shift, mask = tk.mask;
#pragma unroll
    for (int mf = 0; mf < 4; mf++) {
        const int row0 = bm + wm * 64 + mf * 16 + gq;
        const int row1 = row0 + 8;
        const size_t v1b0 = (size_t)((row0 >> shift) & mask) * 1024;
        const size_t v1b1 = (size_t)((row1 >> shift) & mask) * 1024;
        float s0 = 0.f, s1 = 0.f;
#pragma unroll
        for (int nf = 0; nf < 4; nf++) {
            const int col = bn + wn * 32 + nf * 8 + tq * 2;
            const float w0 = w2[col], w1 = w2[col + 1];
            s0 += tanhf(acc[mf][nf][0] + v1[v1b0 + col])     * w0
                + tanhf(acc[mf][nf][1] + v1[v1b0 + col + 1]) * w1;
            s1 += tanhf(acc[mf][nf][2] + v1[v1b1 + col])     * w0
                + tanhf(acc[mf][nf][3] + v1[v1b1 + col + 1]) * w1;
        }
        s0 += __shfl_xor_sync(0xffffffffu, s0, 1);
        s0 += __shfl_xor_sync(0xffffffffu, s0, 2);
        s1 += __shfl_xor_sync(0xffffffffu, s1, 1);
        s1 += __shfl_xor_sync(0xffffffffu, s1, 2);
        if (tq == 0) {
            s_ws[wn][wm * 64 + mf * 16 + gq]     = s0;
            s_ws[wn][wm * 64 + mf * 16 + gq + 8] = s1;
        }
    }
    __syncthreads();
    for (int i = tid; i < 128; i += 256) {
        float v = s_ws[0][i] + s_ws[1][i] + s_ws[2][i] + s_ws[3][i];
        tk.spart[(size_t)blockIdx.x * tk.M + bm + i] = v;
    }
}

// =======================================================================
// General mma.sync TF32 GEMM — now 3-STAGE pipelined (wait_group 1).
// Dynamic smem: 3 * (BM+BN) * LDSS floats = 61440 bytes.
// =======================================================================
#define BM 128
#define BN 128
#define BK 16
#define LDSS 20
#define NST 3
#define GSM_BYTES (NST * (BM + BN) * LDSS * 4)

struct Seg {
    const float* A;
    const float* B;
    long long lda;
    long long ldb;
    int K;
    int pad;
};
struct Task {
    Seg seg[3];
    float* C;
    const float* bias1;
    const float* bias2;
    long long ldc;
    int nseg;
    int pad;
};
struct Tasks4 { Task t[4]; };

__global__ __launch_bounds__(256, 2) void mma_tn_g(int M, int N, Tasks4 ts)
{
    extern __shared__ float dynsm[];
    float (*As)[BM][LDSS] = (float(*)[BM][LDSS])dynsm;
    float (*Bs)[BN][LDSS] = (float(*)[BN][LDSS])(dynsm + NST * BM * LDSS);

    const Task& tk = ts.t[blockIdx.z];

    const int tid  = threadIdx.x;
    const int wid  = tid >> 5, lane = tid & 31;
    const int wm   = wid >> 2;
    const int wn   = wid & 3;
    const int gq   = lane >> 2;
    const int tq   = lane & 3;

    const int bm = blockIdx.y * BM;
    const int bn = blockIdx.x * BN;

    const int lr = tid >> 2;
    const int lc = (tid & 3) << 2;

    float acc[4][4][4];
#pragma unroll
    for (int i = 0; i < 4; i++)
#pragma unroll
        for (int j = 0; j < 4; j++)
#pragma unroll
            for (int v = 0; v < 4; v++) acc[i][j][v] = 0.0f;

    int total_nk = 0;
    for (int i = 0; i < tk.nseg; i++) total_nk += tk.seg[i].K >> 4;

    int psi = 0, pk0 = 0;
    auto prefetch_adv = [&](int st) {
        const float* Aseg = tk.seg[psi].A;
        const float* Bseg = tk.seg[psi].B;
        const long long lda = tk.seg[psi].lda;
        const long long ldb = tk.seg[psi].ldb;
#pragma unroll
        for (int part = 0; part < 2; part++) {
            int r = lr + part * 64;
            const float* asrc = Aseg + (size_t)(bm + r) * lda + pk0 + lc;
            unsigned ad = (unsigned)__cvta_generic_to_shared(&As[st][r][lc]);
            cp_async16(ad, asrc, 16);
            int gn = bn + r;
            int ok = (gn < N);
            const float* bsrc = Bseg + (size_t)(ok ? gn : 0) * ldb + pk0 + lc;
            unsigned bd = (unsigned)__cvta_generic_to_shared(&Bs[st][r][lc]);
            cp_async16(bd, bsrc, ok ? 16 : 0);
        }
        asm volatile("cp.async.commit_group;\n" ::: "memory");
        pk0 += BK;
        if (pk0 >= tk.seg[psi].K) { psi = (psi < 2) ? psi + 1 : psi; pk0 = 0; }
    };

    prefetch_adv(0);
    if (total_nk > 1) prefetch_adv(1);

    int s = 0;
    for (int it = 0; it < total_nk; it++) {
        if (it == total_nk - 1)
            asm volatile("cp.async.wait_group 0;\n" ::: "memory");
        else
            asm volatile("cp.async.wait_group 1;\n" ::: "memory");
        __syncthreads();
        if (it + 2 < total_nk) {
            int st = s + 2; if (st >= NST) st -= NST;
            prefetch_adv(st);
        }

#pragma unroll
        for (int kk = 0; kk < BK; kk += 8) {
            unsigned af[4][4], bfr[4][2];
#pragma unroll
            for (int mf = 0; mf < 4; mf++) {
                const int mr = wm * 64 + mf * 16;
                af[mf][0] = cvt_tf32(As[s][mr + gq    ][kk + tq    ]);
                af[mf][1] = cvt_tf32(As[s][mr + gq + 8][kk + tq    ]);
                af[mf][2] = cvt_tf32(As[s][mr + gq    ][kk + tq + 4]);
                af[mf][3] = cvt_tf32(As[s][mr + gq + 8][kk + tq + 4]);
            }
#pragma unroll
            for (int nf = 0; nf < 4; nf++) {
                const int nr = wn * 32 + nf * 8;
                bfr[nf][0] = cvt_tf32(Bs[s][nr + gq][kk + tq    ]);
                bfr[nf][1] = cvt_tf32(Bs[s][nr + gq][kk + tq + 4]);
            }
#pragma unroll
            for (int mf = 0; mf < 4; mf++)
#pragma unroll
                for (int nf = 0; nf < 4; nf++) {
                    float* c = acc[mf][nf];
                    asm volatile(
                        "mma.sync.aligned.m16n8k8.row.col.f32.tf32.tf32.f32 "
                        "{%0,%1,%2,%3}, {%4,%5,%6,%7}, {%8,%9}, {%0,%1,%2,%3};\n"
                        : "+f"(c[0]), "+f"(c[1]), "+f"(c[2]), "+f"(c[3])
                        : "r"(af[mf][0]), "r"(af[mf][1]), "r"(af[mf][2]), "r"(af[mf][3]),
                          "r"(bfr[nf][0]), "r"(bfr[nf][1]));
                }
        }
        if (++s == NST) s = 0;
    }

    float* C = tk.C;
    const long long ldc = tk.ldc;
    const float* b1 = tk.bias1;
    const float* b2 = tk.bias2;
#pragma unroll
    for (int mf = 0; mf < 4; mf++) {
        const int row = bm + wm * 64 + mf * 16 + gq;
#pragma unroll
        for (int nf = 0; nf < 4; nf++) {
            const int col = bn + wn * 32 + nf * 8 + tq * 2;
            if (col < N) {
                float2 v0 = make_float2(acc[mf][nf][0], acc[mf][nf][1]);
                float2 v1x = make_float2(acc[mf][nf][2], acc[mf][nf][3]);
                if (b1) {
                    float bx = b1[col], by = b1[col + 1];
                    v0.x += bx; v0.y += by; v1x.x += bx; v1x.y += by;
                }
                if (b2) {
                    float bx = b2[col], by = b2[col + 1];
                    v0.x += bx; v0.y += by; v1x.x += bx; v1x.y += by;
                }
                size_t i0 = (size_t)row * ldc + col;
                size_t i1 = (size_t)(row + 8) * ldc + col;
                *reinterpret_cast<float2*>(&C[i0]) = v0;
                *reinterpret_cast<float2*>(&C[i1]) = v1x;
            }
        }
    }
}

// ---------------- attention part 2, z-batched, float4 context ------------
// grid (B, 1, 3), 256 threads; each thread owns 4 consecutive d (float4),
// 8-way independent t accumulation.
struct ATask {
    const float* spart;
    const float* vec2;
    float* out;
    int T;
    int nb;
    int Msp;
    int sp_sb;
    int sp_st;
    int pad;
    long long vv_sb;
    long long vv_st;
    long long out_sb;
};
struct ATasks { ATask t[3]; };

__global__ __launch_bounds__(256) void attn2z(ATasks ts)
{
    __shared__ float s_score[128];
    __shared__ float s_red[256];

    const ATask& a = ts.t[blockIdx.z];
    const int T = a.T, nb = a.nb, Msp = a.Msp;
    const int b = blockIdx.x;
    const int tid = threadIdx.x;

    for (int t = tid; t < T; t += 256) {
        float s = 0.f;
        const float* p = a.spart + (size_t)b * a.sp_sb + (size_t)t * a.sp_st;
#pragma unroll
        for (int k = 0; k < 8; k++)
            if (k < nb) s += p[(size_t)k * Msp];
        s_score[t] = s;
    }
    __syncthreads();

    float m = -1e30f;
    for (int t = tid; t < T; t += 256) m = fmaxf(m, s_score[t]);
    s_red[tid] = m;
    __syncthreads();
    for (int s = 128; s > 0; s >>= 1) {
        if (tid < s) s_red[tid] = fmaxf(s_red[tid], s_red[tid + s]);
        __syncthreads();
    }
    const float mx = s_red[0];
    __syncthreads();
    float lsum = 0.f;
    for (int t = tid; t < T; t += 256) {
        float e = expf(s_score[t] - mx);
        s_score[t] = e;
        lsum += e;
    }
    s_red[tid] = lsum;
    __syncthreads();
    for (int s = 128; s > 0; s >>= 1) {
        if (tid < s) s_red[tid] += s_red[tid + s];
        __syncthreads();
    }
    const float inv = 1.0f / s_red[0];

    // context: thread owns float4 at d = tid*4; 8 independent t-chains.
    const float4* base = (const float4*)(a.vec2 + (size_t)b * a.vv_sb) + tid;
    const size_t st4 = (size_t)(a.vv_st >> 2);
    float4 ac[8];
#pragma unroll
    for (int k = 0; k < 8; k++) ac[k] = make_float4(0.f, 0.f, 0.f, 0.f);

    for (int t = 0; t < T; t += 8) {
#pragma unroll
        for (int k = 0; k < 8; k++) {
            const float sc = s_score[t + k];
            const float4 v = base[(size_t)(t + k) * st4];
            ac[k].x = fmaf(sc, v.x, ac[k].x);
            ac[k].y = fmaf(sc, v.y, ac[k].y);
            ac[k].z = fmaf(sc, v.z, ac[k].z);
            ac[k].w = fmaf(sc, v.w, ac[k].w);
        }
    }
    float4 r;
    r.x = (((ac[0].x + ac[1].x) + (ac[2].x + ac[3].x)) +
           ((ac[4].x + ac[5].x) + (ac[6].x + ac[7].x))) * inv;
    r.y = (((ac[0].y + ac[1].y) + (ac[2].y + ac[3].y)) +
           ((ac[4].y + ac[5].y) + (ac[6].y + ac[7].y))) * inv;
    r.z = (((ac[0].z + ac[1].z) + (ac[2].z + ac[3].z)) +
           ((ac[4].z + ac[5].z) + (ac[6].z + ac[7].z))) * inv;
    r.w = (((ac[0].w + ac[1].w) + (ac[2].w + ac[3].w)) +
           ((ac[4].w + ac[5].w) + (ac[6].w + ac[7].w))) * inv;
    ((float4*)(a.out + (size_t)b * a.out_sb))[tid] = r;
}

// ---------------- fused attention (tiny final T=3) ------
__global__ __launch_bounds__(256) void attn_ctx(
    int T, int E, int D,
    const float* __restrict__ v1,
    const float* __restrict__ v2, long long v2_sb, long long v2_st,
    const float* __restrict__ w2,
    const float* __restrict__ vec2, long long vv_sb, long long vv_st,
    float* __restrict__ out, long long out_sb)
{
    __shared__ float s_v1[1024];
    __shared__ float s_w2[1024];
    __shared__ float s_score[128];
    __shared__ float s_red[256];

    const int b = blockIdx.x;
    const int tid = threadIdx.x;
    for (int j = tid; j < E; j += 256) {
        s_v1[j] = v1[(size_t)b * E + j];
        s_w2[j] = w2[j];
    }
    __syncthreads();

    const int warp = tid >> 5, lane = tid & 31;
    for (int t = warp; t < T; t += 8) {
        const float* p = v2 + (long long)b * v2_sb + (long long)t * v2_st;
        float sum = 0.f;
        for (int j = lane; j < E; j += 32)
            sum += tanhf(s_v1[j] + p[j]) * s_w2[j];
#pragma unroll
        for (int o = 16; o > 0; o >>= 1) sum += __shfl_xor_sync(0xffffffffu, sum, o);
        if (lane == 0) s_score[t] = sum;
    }
    __syncthreads();

    float m = -1e30f;
    for (int t = tid; t < T; t += 256) m = fmaxf(m, s_score[t]);
    s_red[tid] = m;
    __syncthreads();
    for (int s = 128; s > 0; s >>= 1) {
        if (tid < s) s_red[tid] = fmaxf(s_red[tid], s_red[tid + s]);
        __syncthreads();
    }
    const float mx = s_red[0];
    __syncthreads();
    float lsum = 0.f;
    for (int t = tid; t < T; t += 256) {
        float e = expf(s_score[t] - mx);
        s_score[t] = e;
        lsum += e;
    }
    s_red[tid] = lsum;
    __syncthreads();
    for (int s = 128; s > 0; s >>= 1) {
        if (tid < s) s_red[tid] += s_red[tid + s];
        __syncthreads();
    }
    const float inv = 1.0f / s_red[0];

    for (int d = tid; d < D; d += 256) {
        const float* base = vec2 + (long long)b * vv_sb + d;
        float accd = 0.f;
        for (int t = 0; t < T; t++)
            accd += s_score[t] * base[(long long)t * vv_st];
        out[(long long)b * out_sb + d] = accd * inv;
    }
}

// ---------------- LSTM cell: sums 3 gate partials + biases ----------------
__global__ void lstm_cell3(const float* __restrict__ g0,
                           const float* __restrict__ g1,
                           const float* __restrict__ g2,
                           const float* __restrict__ b_ih,
                           const float* __restrict__ b_hh,
                           const float* __restrict__ cell,
                           float* __restrict__ h_out,
                           float* __restrict__ c_out)
{
    int idx = blockIdx.x * blockDim.x + threadIdx.x;   // 0..131071
    int b = idx >> 10, j = idx & 1023;
    size_t base = (size_t)b * 4096;
    float gi = g0[base + j]        + g1[base + j]        + g2[base + j]
             + b_ih[j]             + b_hh[j];
    float gf = g0[base + 1024 + j] + g1[base + 1024 + j] + g2[base + 1024 + j]
             + b_ih[1024 + j]      + b_hh[1024 + j];
    float gg = g0[base + 2048 + j] + g1[base + 2048 + j] + g2[base + 2048 + j]
             + b_ih[2048 + j]      + b_hh[2048 + j];
    float go = g0[base + 3072 + j] + g1[base + 3072 + j] + g2[base + 3072 + j]
             + b_ih[3072 + j]      + b_hh[3072 + j];
    float i_ = 1.f / (1.f + expf(-gi));
    float f_ = 1.f / (1.f + expf(-gf));
    float g_ = tanhf(gg);
    float o_ = 1.f / (1.f + expf(-go));
    float c = f_ * cell[idx] + i_ * g_;
    float h = o_ * tanhf(c);
    c_out[idx] = c;
    h_out[idx] = h;
}

// ---------------- host-side task builders ----------------
static Task mk_task(const float* A, long long lda, const float* B, long long ldb,
                    int K, float* C, long long ldc,
                    const float* b1, const float* b2)
{
    Task t;
    for (int i = 0; i < 3; i++) { t.seg[i].A = A; t.seg[i].B = B; t.seg[i].lda = lda;
                                  t.seg[i].ldb = ldb; t.seg[i].K = K; t.seg[i].pad = 0; }
    t.nseg = 1; t.C = C; t.ldc = ldc; t.bias1 = b1; t.bias2 = b2; t.pad = 0;
    return t;
}

static void launch_tasks(int M, int N, const Task* tasks, int nz)
{
    Tasks4 ts;
    for (int i = 0; i < 4; i++) ts.t[i] = tasks[i < nz ? i : 0];
    dim3 grid((N + BN - 1) / BN, M / BM, nz);
    mma_tn_g<<<grid, 256, GSM_BYTES>>>(M, N, ts);
}

extern "C" void kernel_launch(void* const* d_in, const int* in_sizes, int n_in,
                              void* d_out, int out_size)
{
    const float* input   = (const float*)d_in[0];   // [128,1,1024]
    const float* visual  = (const float*)d_in[1];   // [128,128,1024]
    const float* audio   = (const float*)d_in[2];   // [128,128,1024]
    const float* hstates = (const float*)d_in[3];   // [16,128,1024]
    const float* cell    = (const float*)d_in[4];   // [128,1024]
    const float* context = (const float*)d_in[5];   // [128,1,512]
    const float* Wv0 = (const float*)d_in[6];
    const float* Wv1 = (const float*)d_in[7];
    const float* Wv2 = (const float*)d_in[8];
    const float* Wa0 = (const float*)d_in[9];
    const float* Wa1 = (const float*)d_in[10];
    const float* Wa2 = (const float*)d_in[11];
    const float* Wh0 = (const float*)d_in[12];
    const float* Wh1 = (const float*)d_in[13];
    const float* Wh2 = (const float*)d_in[14];
    const float* Wc0 = (const float*)d_in[15];
    const float* Wc1 = (const float*)d_in[16];
    const float* Wc2 = (const float*)d_in[17];
    const float* Wac = (const float*)d_in[18];
    const float* bac = (const float*)d_in[19];
    const float* Wvc = (const float*)d_in[20];
    const float* bvc = (const float*)d_in[21];
    const float* Whc = (const float*)d_in[22];
    const float* bhc = (const float*)d_in[23];
    const float* W_ih = (const float*)d_in[24];     // [4096,1536]
    const float* W_hh = (const float*)d_in[25];     // [4096,1024]
    const float* b_ih = (const float*)d_in[26];
    const float* b_hh = (const float*)d_in[27];
    const float* W_out = (const float*)d_in[28];    // [20000,1024]
    const float* b_out = (const float*)d_in[29];

    float* out = (float*)d_out;
    float* out_logits = out;
    float* out_h      = out + 2560000;
    float* out_c      = out + 2560000 + 131072;
    float* out_fctx   = out + 2560000 + 131072 + 131072;

    float *spv, *spa, *sph, *v1v, *v1a, *v1h, *ctxv, *ctxa, *ctxh,
          *cstack, *v1c, *v2c, *gat0, *gat1, *gat2,
          *vr, *ar, *hr, *w1v, *w1a, *w1h;
    cudaGetSymbolAddress((void**)&spv, g_spart_v);
    cudaGetSymbolAddress((void**)&spa, g_spart_a);
    cudaGetSymbolAddress((void**)&sph, g_spart_h);
    cudaGetSymbolAddress((void**)&v1v, g_v1v);
    cudaGetSymbolAddress((void**)&v1a, g_v1a);
    cudaGetSymbolAddress((void**)&v1h, g_v1h);
    cudaGetSymbolAddress((void**)&ctxv, g_ctxv);
    cudaGetSymbolAddress((void**)&ctxa, g_ctxa);
    cudaGetSymbolAddress((void**)&ctxh, g_ctxh);
    cudaGetSymbolAddress((void**)&cstack, g_cstack);
    cudaGetSymbolAddress((void**)&v1c, g_v1c);
    cudaGetSymbolAddress((void**)&v2c, g_v2c);
    cudaGetSymbolAddress((void**)&gat0, g_gates0);
    cudaGetSymbolAddress((void**)&gat1, g_gates1);
    cudaGetSymbolAddress((void**)&gat2, g_gates2);
    cudaGetSymbolAddress((void**)&vr, g_vr);
    cudaGetSymbolAddress((void**)&ar, g_ar);
    cudaGetSymbolAddress((void**)&hr, g_hr);
    cudaGetSymbolAddress((void**)&w1v, g_w1v);
    cudaGetSymbolAddress((void**)&w1a, g_w1a);
    cudaGetSymbolAddress((void**)&w1h, g_w1h);

    cudaFuncSetAttribute(mma_tn_g, cudaFuncAttributeMaxDynamicSharedMemorySize,
                         GSM_BYTES);

    const float* hidden = hstates + (size_t)15 * 128 * 1024;  // hidden_states[-1]

    // [1..3] round+permute activations
    round_perm_tf32<<<4096, 256>>>((const float4*)visual, (float4*)vr, 1048576);
    round_perm_tf32<<<4096, 256>>>((const float4*)audio, (float4*)ar, 1048576);
    round_perm_tf32<<<512, 256>>>((const float4*)hstates, (float4*)hr, 131072);
    // [4] query projections (3 tasks, ONE launch) — ncu-profiled slot
    {
        Task t[3] = {
            mk_task(context, 512, Wv0, 512, 512, v1v, 1024, nullptr, nullptr),
            mk_task(context, 512, Wa0, 512, 512, v1a, 1024, nullptr, nullptr),
            mk_task(context, 512, Wh0, 512, 512, v1h, 1024, nullptr, nullptr),
        };
        launch_tasks(128, 1024, t, 3);
    }
    // [5] round+permute the 3 weight matrices, batched (z=3)
    {
        RPW w;
        w.src[0] = (const float4*)Wv1; w.dst[0] = (float4*)w1v;
        w.src[1] = (const float4*)Wa1; w.dst[1] = (float4*)w1a;
        w.src[2] = (const float4*)Wh1; w.dst[2] = (float4*)w1h;
        round_perm_tf32_z<<<dim3(256, 1, 3), 256>>>(w, 65536);
    }
    // [6] fast score GEMMs: visual + audio + hidden, ONE launch
    {
        STasks st;
        st.t[0] = { vr, w1v, v1v, Wv2, spv, 16384, 7, 127, 0 };
        st.t[1] = { ar, w1a, v1a, Wa2, spa, 16384, 7, 127, 0 };
        st.t[2] = { hr, w1h, v1h, Wh2, sph, 2048,  0, 127, 0 };
        mma_perm<<<dim3(8, 128, 3), 256>>>(st, 1024 / PKT);
    }

    // [7] attention part 2: visual + audio + hidden in ONE z=3 launch
    {
        ATasks at;
        at.t[0] = { spv, visual,  ctxv, 128, 8, 16384, 128, 1,   0, 128 * 1024, 1024,       1024 };
        at.t[1] = { spa, audio,   ctxa, 128, 8, 16384, 128, 1,   0, 128 * 1024, 1024,       1024 };
        at.t[2] = { sph, hstates, ctxh, 16,  8, 2048,  1,   128, 0, 1024,       128 * 1024, 1024 };
        attn2z<<<dim3(128, 1, 3), 256>>>(at);
    }

    // --- context stack (3 tasks) + Wc0 query projection (1 task): ONE launch ---
    {
        Task t[4] = {
            mk_task(ctxa,   1024, Wac, 1024, 1024, cstack + 0,    1536, bac, nullptr),
            mk_task(ctxv,   1024, Wvc, 1024, 1024, cstack + 512,  1536, bvc, nullptr),
            mk_task(ctxh,   1024, Whc, 1024, 1024, cstack + 1024, 1536, bhc, nullptr),
            mk_task(hidden, 1024, Wc0, 1024, 1024, v1c,           512,  nullptr, nullptr),
        };
        launch_tasks(128, 512, t, 4);
    }

    // --- v2c = cstack @ Wc1^T ---
    {
        Task t = mk_task(cstack, 512, Wc1, 512, 512, v2c, 512, nullptr, nullptr);
        launch_tasks(384, 512, &t, 1);
    }
    attn_ctx<<<128, 256>>>(3, 512, 512, v1c, v2c, 3 * 512, 512, Wc2,
                           cstack, 3 * 512, 512, out_fctx, 512);

    // --- LSTM gates: 3 K-segments as 3 PARALLEL z-tasks (partials) ---
    {
        Task t[3] = {
            mk_task(out_fctx, 512,  W_ih,       1536, 512,  gat0, 4096, nullptr, nullptr),
            mk_task(input,    1024, W_ih + 512, 1536, 1024, gat1, 4096, nullptr, nullptr),
            mk_task(hidden,   1024, W_hh,       1024, 1024, gat2, 4096, nullptr, nullptr),
        };
        launch_tasks(128, 4096, t, 3);
    }

    lstm_cell3<<<512, 256>>>(gat0, gat1, gat2, b_ih, b_hh, cell, out_h, out_c);

    // --- logits = h_new @ W_out^T + b_out ---
    {
        Task t = mk_task(out_h, 1024, W_out, 1024, 1024, out_logits, 20000, b_out, nullptr);
        launch_tasks(128, 20000, &t, 1);
    }
}